// round 1
// baseline (speedup 1.0000x reference)
#include <cuda_runtime.h>
#include <cuda_bf16.h>

#define BB 4
#define SS 4096
#define DIN 512
#define DD 256
#define TQ 64
#define TK 64

// Scratch for projected Q, K (device globals: no allocation allowed)
__device__ float g_Q[BB * SS * DD];
__device__ float g_K[BB * SS * DD];

// ---------------------------------------------------------------------------
// Projection: out[row, d] = sum_i X[row, i] * W[d, i] + bias[d]
// X: [16384, 512], W: [256, 512], out: [16384, 256]
// Block: 64 rows x all 256 cols. 256 threads, each 2 rows x 32 cols.
// ---------------------------------------------------------------------------
__global__ __launch_bounds__(256, 2)
void proj_kernel(const float* __restrict__ X, const float* __restrict__ W,
                 const float* __restrict__ bias, int dst)
{
    __shared__ float sX[64 * 36];    // 64 rows x 32 (+4 pad)
    __shared__ float sW[256 * 36];   // 256 rows x 32 (+4 pad)

    float* out = dst ? g_K : g_Q;
    const int tid  = threadIdx.x;
    const int row0 = blockIdx.x * 64;
    const int r0 = tid & 31, r1 = r0 + 32;
    const int c0 = (tid >> 5) * 32;

    float acc0[32], acc1[32];
#pragma unroll
    for (int c = 0; c < 32; c += 4) {
        float4 bv = *(const float4*)&bias[c0 + c];
        acc0[c] = bv.x; acc0[c+1] = bv.y; acc0[c+2] = bv.z; acc0[c+3] = bv.w;
        acc1[c] = bv.x; acc1[c+1] = bv.y; acc1[c+2] = bv.z; acc1[c+3] = bv.w;
    }

    for (int i0 = 0; i0 < DIN; i0 += 32) {
#pragma unroll
        for (int u = tid; u < 64 * 8; u += 256) {
            int r = u >> 3, f = u & 7;
            *(float4*)&sX[r * 36 + f * 4] =
                *(const float4*)&X[(row0 + r) * DIN + i0 + f * 4];
        }
#pragma unroll
        for (int u = tid; u < 256 * 8; u += 256) {
            int r = u >> 3, f = u & 7;
            *(float4*)&sW[r * 36 + f * 4] =
                *(const float4*)&W[r * DIN + i0 + f * 4];
        }
        __syncthreads();

#pragma unroll
        for (int ii = 0; ii < 32; ii += 4) {
            float4 xa = *(const float4*)&sX[r0 * 36 + ii];
            float4 xb = *(const float4*)&sX[r1 * 36 + ii];
#pragma unroll
            for (int c = 0; c < 32; c++) {
                float4 w = *(const float4*)&sW[(c0 + c) * 36 + ii];
                acc0[c] += xa.x * w.x;
                acc0[c] += xa.y * w.y;
                acc0[c] += xa.z * w.z;
                acc0[c] += xa.w * w.w;
                acc1[c] += xb.x * w.x;
                acc1[c] += xb.y * w.y;
                acc1[c] += xb.z * w.z;
                acc1[c] += xb.w * w.w;
            }
        }
        __syncthreads();
    }

#pragma unroll
    for (int c = 0; c < 32; c += 4) {
        *(float4*)&out[(row0 + r0) * DD + c0 + c] =
            make_float4(acc0[c], acc0[c+1], acc0[c+2], acc0[c+3]);
        *(float4*)&out[(row0 + r1) * DD + c0 + c] =
            make_float4(acc1[c], acc1[c+1], acc1[c+2], acc1[c+3]);
    }
}

// ---------------------------------------------------------------------------
// Flash attention, fp32. One CTA = 64 query rows of one batch.
// Stream over 64-key tiles: S = Q Kt (regs, 4q x 4k per thread),
// online softmax (shuffle within 16-lane groups + shared m/l/scale),
// P staged in shared (stride 65: conflict-free), O accum 2q x 32d per thread.
// ---------------------------------------------------------------------------
#define SQ_STRIDE 260
#define SK_STRIDE 260
#define SP_STRIDE 65

__global__ __launch_bounds__(256, 1)
void attn_kernel(const float* __restrict__ value, const float* __restrict__ sfp,
                 float* __restrict__ out)
{
    extern __shared__ float smem[];
    float* sQ  = smem;                       // 64*260
    float* sK  = sQ + 64 * SQ_STRIDE;        // 64*260
    float* sV  = sK + 64 * SK_STRIDE;        // 64*256
    float* sP  = sV + 64 * 256;              // 64*65
    float* smx = sP + 64 * SP_STRIDE;        // 64 running max
    float* sl  = smx + 64;                   // 64 running sum
    float* ssc = sl + 64;                    // 64 rescale factor

    const int tid = threadIdx.x;
    const int b   = blockIdx.x >> 6;
    const int q0  = (blockIdx.x & 63) * TQ;
    const float sf = *sfp;

    const int tr = tid >> 4, tc = tid & 15;      // score phase: 16x16 thread grid
    const int qo0 = tid & 31, qo1 = qo0 + 32;    // PV phase: 2 q rows
    const int dcg = (tid >> 5) * 32;             // PV phase: 32 d cols

    // Load Q tile once
    for (int u = tid; u < 64 * 64; u += 256) {
        int r = u >> 6, c4 = (u & 63) * 4;
        *(float4*)&sQ[r * SQ_STRIDE + c4] =
            *(const float4*)&g_Q[(b * SS + q0 + r) * DD + c4];
    }
    if (tid < 64) { smx[tid] = -1e30f; sl[tid] = 0.0f; }

    float acc0[32], acc1[32];
#pragma unroll
    for (int c = 0; c < 32; c++) { acc0[c] = 0.0f; acc1[c] = 0.0f; }

    for (int kt = 0; kt < SS / TK; kt++) {
        const int k0 = kt * TK;
        for (int u = tid; u < 64 * 64; u += 256) {
            int r = u >> 6, c4 = (u & 63) * 4;
            *(float4*)&sK[r * SK_STRIDE + c4] =
                *(const float4*)&g_K[(b * SS + k0 + r) * DD + c4];
            *(float4*)&sV[r * 256 + c4] =
                *(const float4*)&value[(b * SS + k0 + r) * DD + c4];
        }
        __syncthreads();

        // ---- scores: 4q x 4k per thread, dot over D=256 ----
        float s[4][4];
#pragma unroll
        for (int i = 0; i < 4; i++)
#pragma unroll
            for (int j = 0; j < 4; j++) s[i][j] = 0.0f;

        for (int d = 0; d < DD; d += 4) {
            float4 qa[4], kb[4];
#pragma unroll
            for (int i = 0; i < 4; i++)
                qa[i] = *(const float4*)&sQ[(tr + 16 * i) * SQ_STRIDE + d];
#pragma unroll
            for (int j = 0; j < 4; j++)
                kb[j] = *(const float4*)&sK[(tc + 16 * j) * SK_STRIDE + d];
#pragma unroll
            for (int i = 0; i < 4; i++)
#pragma unroll
                for (int j = 0; j < 4; j++) {
                    s[i][j] += qa[i].x * kb[j].x;
                    s[i][j] += qa[i].y * kb[j].y;
                    s[i][j] += qa[i].z * kb[j].z;
                    s[i][j] += qa[i].w * kb[j].w;
                }
        }
#pragma unroll
        for (int i = 0; i < 4; i++)
#pragma unroll
            for (int j = 0; j < 4; j++) s[i][j] *= sf;

        // ---- online softmax ----
#pragma unroll
        for (int i = 0; i < 4; i++) {
            const int qr = tr + 16 * i;
            float mx = fmaxf(fmaxf(s[i][0], s[i][1]), fmaxf(s[i][2], s[i][3]));
#pragma unroll
            for (int o = 1; o < 16; o <<= 1)
                mx = fmaxf(mx, __shfl_xor_sync(0xffffffffu, mx, o));
            const float m_old = smx[qr];
            const float m_new = fmaxf(m_old, mx);
            float rs = 0.0f;
#pragma unroll
            for (int j = 0; j < 4; j++) {
                float p = __expf(s[i][j] - m_new);
                sP[qr * SP_STRIDE + tc + 16 * j] = p;
                rs += p;
            }
#pragma unroll
            for (int o = 1; o < 16; o <<= 1)
                rs += __shfl_xor_sync(0xffffffffu, rs, o);
            if (tc == 0) {
                float sc = __expf(m_old - m_new);
                ssc[qr] = sc;
                sl[qr]  = sl[qr] * sc + rs;
                smx[qr] = m_new;
            }
        }
        __syncthreads();

        // ---- O = O*scale + P @ V ----
        const float sc0 = ssc[qo0], sc1 = ssc[qo1];
#pragma unroll
        for (int c = 0; c < 32; c++) { acc0[c] *= sc0; acc1[c] *= sc1; }

        for (int k = 0; k < TK; k++) {
            const float p0 = sP[qo0 * SP_STRIDE + k];
            const float p1 = sP[qo1 * SP_STRIDE + k];
            const float4* vr = (const float4*)&sV[k * 256 + dcg];
#pragma unroll
            for (int jj = 0; jj < 8; jj++) {
                float4 v = vr[jj];
                acc0[jj*4+0] += p0 * v.x;
                acc0[jj*4+1] += p0 * v.y;
                acc0[jj*4+2] += p0 * v.z;
                acc0[jj*4+3] += p0 * v.w;
                acc1[jj*4+0] += p1 * v.x;
                acc1[jj*4+1] += p1 * v.y;
                acc1[jj*4+2] += p1 * v.z;
                acc1[jj*4+3] += p1 * v.w;
            }
        }
        __syncthreads();
    }

    const float inv0 = 1.0f / sl[qo0];
    const float inv1 = 1.0f / sl[qo1];
#pragma unroll
    for (int c = 0; c < 32; c += 4) {
        *(float4*)&out[(b * SS + q0 + qo0) * DD + dcg + c] =
            make_float4(acc0[c]*inv0, acc0[c+1]*inv0, acc0[c+2]*inv0, acc0[c+3]*inv0);
        *(float4*)&out[(b * SS + q0 + qo1) * DD + dcg + c] =
            make_float4(acc1[c]*inv1, acc1[c+1]*inv1, acc1[c+2]*inv1, acc1[c+3]*inv1);
    }
}

// ---------------------------------------------------------------------------
extern "C" void kernel_launch(void* const* d_in, const int* in_sizes, int n_in,
                              void* d_out, int out_size)
{
    const float* query = (const float*)d_in[0];
    const float* key   = (const float*)d_in[1];
    const float* value = (const float*)d_in[2];
    const float* Wq    = (const float*)d_in[3];
    const float* bq    = (const float*)d_in[4];
    const float* Wk    = (const float*)d_in[5];
    const float* bk    = (const float*)d_in[6];
    const float* sf    = (const float*)d_in[7];
    float* out = (float*)d_out;

    const int attn_smem = (64 * SQ_STRIDE + 64 * SK_STRIDE + 64 * 256 +
                           64 * SP_STRIDE + 3 * 64) * (int)sizeof(float);
    cudaFuncSetAttribute(attn_kernel, cudaFuncAttributeMaxDynamicSharedMemorySize,
                         attn_smem);

    proj_kernel<<<(BB * SS) / 64, 256>>>(query, Wq, bq, 0);
    proj_kernel<<<(BB * SS) / 64, 256>>>(key,   Wk, bk, 1);
    attn_kernel<<<BB * (SS / TQ), 256, attn_smem>>>(value, sf, out);
}

// round 2
// speedup vs baseline: 1.0018x; 1.0018x over previous
#include <cuda_runtime.h>
#include <cuda_bf16.h>

#define BB 4
#define SS 4096
#define DIN 512
#define DD 256
#define TQ 64
#define TK 64

// Scratch for projected Q, K (device globals: no allocation allowed)
__device__ float g_Q[BB * SS * DD];
__device__ float g_K[BB * SS * DD];

// ---------------------------------------------------------------------------
// Projection: out[row, d] = sum_i X[row, i] * W[d, i] + bias[d]
// X: [16384, 512], W: [256, 512], out: [16384, 256]
// Block: 64 rows x all 256 cols. 256 threads, each 2 rows x 32 cols.
// ---------------------------------------------------------------------------
__global__ __launch_bounds__(256, 2)
void proj_kernel(const float* __restrict__ X, const float* __restrict__ W,
                 const float* __restrict__ bias, int dst)
{
    __shared__ float sX[64 * 36];    // 64 rows x 32 (+4 pad)
    __shared__ float sW[256 * 36];   // 256 rows x 32 (+4 pad)

    float* out = dst ? g_K : g_Q;
    const int tid  = threadIdx.x;
    const int row0 = blockIdx.x * 64;
    const int r0 = tid & 31, r1 = r0 + 32;
    const int c0 = (tid >> 5) * 32;

    float acc0[32], acc1[32];
#pragma unroll
    for (int c = 0; c < 32; c += 4) {
        float4 bv = *(const float4*)&bias[c0 + c];
        acc0[c] = bv.x; acc0[c+1] = bv.y; acc0[c+2] = bv.z; acc0[c+3] = bv.w;
        acc1[c] = bv.x; acc1[c+1] = bv.y; acc1[c+2] = bv.z; acc1[c+3] = bv.w;
    }

    for (int i0 = 0; i0 < DIN; i0 += 32) {
#pragma unroll
        for (int u = tid; u < 64 * 8; u += 256) {
            int r = u >> 3, f = u & 7;
            *(float4*)&sX[r * 36 + f * 4] =
                *(const float4*)&X[(row0 + r) * DIN + i0 + f * 4];
        }
#pragma unroll
        for (int u = tid; u < 256 * 8; u += 256) {
            int r = u >> 3, f = u & 7;
            *(float4*)&sW[r * 36 + f * 4] =
                *(const float4*)&W[r * DIN + i0 + f * 4];
        }
        __syncthreads();

#pragma unroll
        for (int ii = 0; ii < 32; ii += 4) {
            float4 xa = *(const float4*)&sX[r0 * 36 + ii];
            float4 xb = *(const float4*)&sX[r1 * 36 + ii];
#pragma unroll
            for (int c = 0; c < 32; c++) {
                float4 w = *(const float4*)&sW[(c0 + c) * 36 + ii];
                acc0[c] += xa.x * w.x;
                acc0[c] += xa.y * w.y;
                acc0[c] += xa.z * w.z;
                acc0[c] += xa.w * w.w;
                acc1[c] += xb.x * w.x;
                acc1[c] += xb.y * w.y;
                acc1[c] += xb.z * w.z;
                acc1[c] += xb.w * w.w;
            }
        }
        __syncthreads();
    }

#pragma unroll
    for (int c = 0; c < 32; c += 4) {
        *(float4*)&out[(row0 + r0) * DD + c0 + c] =
            make_float4(acc0[c], acc0[c+1], acc0[c+2], acc0[c+3]);
        *(float4*)&out[(row0 + r1) * DD + c0 + c] =
            make_float4(acc1[c], acc1[c+1], acc1[c+2], acc1[c+3]);
    }
}

// ---------------------------------------------------------------------------
// Flash attention, fp32. One CTA = 64 query rows of one batch.
// Stream over 64-key tiles: S = Q Kt (regs, 4q x 4k per thread),
// online softmax (shuffle within 16-lane groups + shared m/l/scale),
// P staged in shared (stride 65: conflict-free), O accum 2q x 32d per thread.
// ---------------------------------------------------------------------------
#define SQ_STRIDE 260
#define SK_STRIDE 260
#define SP_STRIDE 65

__global__ __launch_bounds__(256, 1)
void attn_kernel(const float* __restrict__ value, const float* __restrict__ sfp,
                 float* __restrict__ out)
{
    extern __shared__ float smem[];
    float* sQ  = smem;                       // 64*260
    float* sK  = sQ + 64 * SQ_STRIDE;        // 64*260
    float* sV  = sK + 64 * SK_STRIDE;        // 64*256
    float* sP  = sV + 64 * 256;              // 64*65
    float* smx = sP + 64 * SP_STRIDE;        // 64 running max
    float* sl  = smx + 64;                   // 64 running sum
    float* ssc = sl + 64;                    // 64 rescale factor

    const int tid = threadIdx.x;
    const int b   = blockIdx.x >> 6;
    const int q0  = (blockIdx.x & 63) * TQ;
    const float sf = *sfp;

    const int tr = tid >> 4, tc = tid & 15;      // score phase: 16x16 thread grid
    const int qo0 = tid & 31, qo1 = qo0 + 32;    // PV phase: 2 q rows
    const int dcg = (tid >> 5) * 32;             // PV phase: 32 d cols

    // Load Q tile once
    for (int u = tid; u < 64 * 64; u += 256) {
        int r = u >> 6, c4 = (u & 63) * 4;
        *(float4*)&sQ[r * SQ_STRIDE + c4] =
            *(const float4*)&g_Q[(b * SS + q0 + r) * DD + c4];
    }
    if (tid < 64) { smx[tid] = -1e30f; sl[tid] = 0.0f; }

    float acc0[32], acc1[32];
#pragma unroll
    for (int c = 0; c < 32; c++) { acc0[c] = 0.0f; acc1[c] = 0.0f; }

    for (int kt = 0; kt < SS / TK; kt++) {
        const int k0 = kt * TK;
        for (int u = tid; u < 64 * 64; u += 256) {
            int r = u >> 6, c4 = (u & 63) * 4;
            *(float4*)&sK[r * SK_STRIDE + c4] =
                *(const float4*)&g_K[(b * SS + k0 + r) * DD + c4];
            *(float4*)&sV[r * 256 + c4] =
                *(const float4*)&value[(b * SS + k0 + r) * DD + c4];
        }
        __syncthreads();

        // ---- scores: 4q x 4k per thread, dot over D=256 ----
        float s[4][4];
#pragma unroll
        for (int i = 0; i < 4; i++)
#pragma unroll
            for (int j = 0; j < 4; j++) s[i][j] = 0.0f;

        for (int d = 0; d < DD; d += 4) {
            float4 qa[4], kb[4];
#pragma unroll
            for (int i = 0; i < 4; i++)
                qa[i] = *(const float4*)&sQ[(tr + 16 * i) * SQ_STRIDE + d];
#pragma unroll
            for (int j = 0; j < 4; j++)
                kb[j] = *(const float4*)&sK[(tc + 16 * j) * SK_STRIDE + d];
#pragma unroll
            for (int i = 0; i < 4; i++)
#pragma unroll
                for (int j = 0; j < 4; j++) {
                    s[i][j] += qa[i].x * kb[j].x;
                    s[i][j] += qa[i].y * kb[j].y;
                    s[i][j] += qa[i].z * kb[j].z;
                    s[i][j] += qa[i].w * kb[j].w;
                }
        }
#pragma unroll
        for (int i = 0; i < 4; i++)
#pragma unroll
            for (int j = 0; j < 4; j++) s[i][j] *= sf;

        // ---- online softmax ----
#pragma unroll
        for (int i = 0; i < 4; i++) {
            const int qr = tr + 16 * i;
            float mx = fmaxf(fmaxf(s[i][0], s[i][1]), fmaxf(s[i][2], s[i][3]));
#pragma unroll
            for (int o = 1; o < 16; o <<= 1)
                mx = fmaxf(mx, __shfl_xor_sync(0xffffffffu, mx, o));
            const float m_old = smx[qr];
            const float m_new = fmaxf(m_old, mx);
            float rs = 0.0f;
#pragma unroll
            for (int j = 0; j < 4; j++) {
                float p = __expf(s[i][j] - m_new);
                sP[qr * SP_STRIDE + tc + 16 * j] = p;
                rs += p;
            }
#pragma unroll
            for (int o = 1; o < 16; o <<= 1)
                rs += __shfl_xor_sync(0xffffffffu, rs, o);
            if (tc == 0) {
                float sc = __expf(m_old - m_new);
                ssc[qr] = sc;
                sl[qr]  = sl[qr] * sc + rs;
                smx[qr] = m_new;
            }
        }
        __syncthreads();

        // ---- O = O*scale + P @ V ----
        const float sc0 = ssc[qo0], sc1 = ssc[qo1];
#pragma unroll
        for (int c = 0; c < 32; c++) { acc0[c] *= sc0; acc1[c] *= sc1; }

        for (int k = 0; k < TK; k++) {
            const float p0 = sP[qo0 * SP_STRIDE + k];
            const float p1 = sP[qo1 * SP_STRIDE + k];
            const float4* vr = (const float4*)&sV[k * 256 + dcg];
#pragma unroll
            for (int jj = 0; jj < 8; jj++) {
                float4 v = vr[jj];
                acc0[jj*4+0] += p0 * v.x;
                acc0[jj*4+1] += p0 * v.y;
                acc0[jj*4+2] += p0 * v.z;
                acc0[jj*4+3] += p0 * v.w;
                acc1[jj*4+0] += p1 * v.x;
                acc1[jj*4+1] += p1 * v.y;
                acc1[jj*4+2] += p1 * v.z;
                acc1[jj*4+3] += p1 * v.w;
            }
        }
        __syncthreads();
    }

    const float inv0 = 1.0f / sl[qo0];
    const float inv1 = 1.0f / sl[qo1];
#pragma unroll
    for (int c = 0; c < 32; c += 4) {
        *(float4*)&out[(b * SS + q0 + qo0) * DD + dcg + c] =
            make_float4(acc0[c]*inv0, acc0[c+1]*inv0, acc0[c+2]*inv0, acc0[c+3]*inv0);
        *(float4*)&out[(b * SS + q0 + qo1) * DD + dcg + c] =
            make_float4(acc1[c]*inv1, acc1[c+1]*inv1, acc1[c+2]*inv1, acc1[c+3]*inv1);
    }
}

// ---------------------------------------------------------------------------
extern "C" void kernel_launch(void* const* d_in, const int* in_sizes, int n_in,
                              void* d_out, int out_size)
{
    const float* query = (const float*)d_in[0];
    const float* key   = (const float*)d_in[1];
    const float* value = (const float*)d_in[2];
    const float* Wq    = (const float*)d_in[3];
    const float* bq    = (const float*)d_in[4];
    const float* Wk    = (const float*)d_in[5];
    const float* bk    = (const float*)d_in[6];
    const float* sf    = (const float*)d_in[7];
    float* out = (float*)d_out;

    const int attn_smem = (64 * SQ_STRIDE + 64 * SK_STRIDE + 64 * 256 +
                           64 * SP_STRIDE + 3 * 64) * (int)sizeof(float);
    cudaFuncSetAttribute(attn_kernel, cudaFuncAttributeMaxDynamicSharedMemorySize,
                         attn_smem);

    proj_kernel<<<(BB * SS) / 64, 256>>>(query, Wq, bq, 0);
    proj_kernel<<<(BB * SS) / 64, 256>>>(key,   Wk, bk, 1);
    attn_kernel<<<BB * (SS / TQ), 256, attn_smem>>>(value, sf, out);
}

// round 9
// speedup vs baseline: 2.0592x; 2.0555x over previous
#include <cuda_runtime.h>
#include <cuda_bf16.h>
#include <cstdint>
#define BB 4
#define SS 4096
#define DIN 512
#define DD 256
#define KST 264
#define PST 72
#define TSZ 33792
#define PSZ 9216
#define SMP 202752
#define SMR 221184
#define SMT 222976
typedef __nv_bfloat162 bf2;
typedef uint32_t u32;

__device__ __nv_bfloat16 gQ[2][BB*SS*DD], gK[2][BB*SS*DD];

__device__ __forceinline__ void sp2(float a, float b, bf2& h, bf2& l) {
 h.x = __float2bfloat16(a); h.y = __float2bfloat16(b);
 l.x = __float2bfloat16(a - __bfloat162float(h.x));
 l.y = __float2bfloat16(b - __bfloat162float(h.y));
}

__global__ __launch_bounds__(256, 2)
void proj(const float* __restrict__ X, const float* __restrict__ W,
          const float* __restrict__ bias, int dst) {
 __shared__ float sX[64*36], sW[256*36];
 const int tid = threadIdx.x, row0 = blockIdx.x*64;
 const int r0 = tid & 31, r1 = r0 + 32, c0 = (tid >> 5)*32;
 float a0[32], a1[32];
#pragma unroll
 for (int c = 0; c < 32; c++) { a0[c] = bias[c0+c]; a1[c] = a0[c]; }
 for (int i0 = 0; i0 < DIN; i0 += 32) {
#pragma unroll
  for (int u = tid; u < 512; u += 256)
   *(float4*)&sX[(u>>3)*36+(u&7)*4] = *(const float4*)&X[(row0+(u>>3))*DIN+i0+(u&7)*4];
#pragma unroll
  for (int u = tid; u < 2048; u += 256)
   *(float4*)&sW[(u>>3)*36+(u&7)*4] = *(const float4*)&W[(u>>3)*DIN+i0+(u&7)*4];
  __syncthreads();
#pragma unroll
  for (int ii = 0; ii < 32; ii += 4) {
   float4 xa = *(const float4*)&sX[r0*36+ii];
   float4 xb = *(const float4*)&sX[r1*36+ii];
#pragma unroll
   for (int c = 0; c < 32; c++) {
    float4 w = *(const float4*)&sW[(c0+c)*36+ii];
    a0[c] += xa.x*w.x + xa.y*w.y + xa.z*w.z + xa.w*w.w;
    a1[c] += xb.x*w.x + xb.y*w.y + xb.z*w.z + xb.w*w.w;
   }
  }
  __syncthreads();
 }
 __nv_bfloat16* oh = dst ? gK[0] : gQ[0];
 __nv_bfloat16* ol = dst ? gK[1] : gQ[1];
#pragma unroll
 for (int c = 0; c < 32; c += 2) {
  bf2 h, l;
  size_t oa = (size_t)(row0+r0)*DD + c0 + c, ob = (size_t)(row0+r1)*DD + c0 + c;
  sp2(a0[c], a0[c+1], h, l);
  *(bf2*)&oh[oa] = h; *(bf2*)&ol[oa] = l;
  sp2(a1[c], a1[c+1], h, l);
  *(bf2*)&oh[ob] = h; *(bf2*)&ol[ob] = l;
 }
}

__device__ __forceinline__ void lds(u32* r, u32 a) {
 asm volatile("ldmatrix.sync.aligned.m8n8.x4.shared.b16 {%0,%1,%2,%3},[%4];"
  : "=r"(r[0]), "=r"(r[1]), "=r"(r[2]), "=r"(r[3]) : "r"(a));
}
__device__ __forceinline__ void ldt(u32* r, u32 a) {
 asm volatile("ldmatrix.sync.aligned.m8n8.x4.trans.shared.b16 {%0,%1,%2,%3},[%4];"
  : "=r"(r[0]), "=r"(r[1]), "=r"(r[2]), "=r"(r[3]) : "r"(a));
}
__device__ __forceinline__ void mma(float* c, const u32* a, u32 b0, u32 b1) {
 asm volatile("mma.sync.aligned.m16n8k16.row.col.f32.bf16.bf16.f32 "
  "{%0,%1,%2,%3},{%4,%5,%6,%7},{%8,%9},{%0,%1,%2,%3};"
  : "+f"(c[0]), "+f"(c[1]), "+f"(c[2]), "+f"(c[3])
  : "r"(a[0]), "r"(a[1]), "r"(a[2]), "r"(a[3]), "r"(b0), "r"(b1));
}
__device__ __forceinline__ void mma3(float* cA, float* cB, u32 (*A)[4], u32 (*B)[4]) {
 mma(cA, A[0], B[0][0], B[0][1]); mma(cB, A[0], B[0][2], B[0][3]);
 mma(cA, A[0], B[1][0], B[1][1]); mma(cB, A[0], B[1][2], B[1][3]);
 mma(cA, A[1], B[0][0], B[0][1]); mma(cB, A[1], B[0][2], B[0][3]);
}

__global__ __launch_bounds__(256, 1)
void attn(const float* __restrict__ val, const float* __restrict__ sfp,
          float* __restrict__ out) {
 extern __shared__ char sm[];
 const u32 sb = (u32)__cvta_generic_to_shared(sm);
 float* sMx = (float*)(sm + SMR);
 float* sM = sMx + 128;
 float* sL = sMx + 256;
 const int tid = threadIdx.x, lane = tid & 31, wid = tid >> 5;
 const int mb = wid & 3, nb = wid >> 2, t = lane & 3;
 const int b = blockIdx.x >> 6, q0 = (blockIdx.x & 63)*64;
 const float sf = *sfp;

 for (int u = tid; u < 2048; u += 256) {
  int r = u >> 5, c = u & 31;
  size_t gi = (size_t)(b*SS + q0 + r)*DD;
  u32 so = (r*KST + c*8)*2;
  *(uint4*)(sm + so) = ((const uint4*)(gQ[0] + gi))[c];
  *(uint4*)(sm + TSZ + so) = ((const uint4*)(gQ[1] + gi))[c];
 }
 if (tid < 128) { sM[tid] = -1e30f; sL[tid] = 0.f; }

 const int lr = lane & 7, qd = lane >> 3;
 const u32 aoff = ((mb*16 + (lane&15))*KST + (lane>>4)*8)*2;
 const u32 koff = ((nb*32 + (qd>>1)*8 + lr)*KST + (qd&1)*8)*2;
 const u32 voff = (((qd&1)*8 + lr)*KST + nb*128 + (qd>>1)*8)*2;
 const u32 poff = ((mb*16 + (lane&15))*PST + (lane>>4)*8)*2;

 float O[16][4];
#pragma unroll
 for (int j = 0; j < 16; j++) O[j][0] = O[j][1] = O[j][2] = O[j][3] = 0.f;
 int rr[2]; rr[0] = mb*16 + (lane >> 2); rr[1] = rr[0] + 8;

 for (int kt = 0; kt < SS/64; kt++) {
  for (int u = tid; u < 2048; u += 256) {
   int r = u >> 5, c = u & 31;
   size_t gi = (size_t)(b*SS + kt*64 + r)*DD;
   u32 so = (r*KST + c*8)*2;
   *(uint4*)(sm + 2*TSZ + so) = ((const uint4*)(gK[0] + gi))[c];
   *(uint4*)(sm + 3*TSZ + so) = ((const uint4*)(gK[1] + gi))[c];
  }
  for (int u = tid; u < 4096; u += 256) {
   int r = u >> 6, c = u & 63;
   float4 v = ((const float4*)&val[(size_t)(b*SS + kt*64 + r)*DD])[c];
   bf2 ha, la, hb, lb;
   sp2(v.x, v.y, ha, la); sp2(v.z, v.w, hb, lb);
   u32 so = (r*KST + c*4)*2;
   *(bf2*)(sm + 4*TSZ + so) = ha; *(bf2*)(sm + 4*TSZ + so + 4) = hb;
   *(bf2*)(sm + 5*TSZ + so) = la; *(bf2*)(sm + 5*TSZ + so + 4) = lb;
  }
  __syncthreads();

  float Sv[4][4];
#pragma unroll
  for (int j = 0; j < 4; j++) Sv[j][0] = Sv[j][1] = Sv[j][2] = Sv[j][3] = 0.f;
#pragma unroll 4
  for (int kk = 0; kk < 16; kk++) {
   u32 A[2][4], B[2][4];
   lds(A[0], sb + aoff + kk*32);
   lds(A[1], sb + TSZ + aoff + kk*32);
#pragma unroll
   for (int pr = 0; pr < 2; pr++) {
    u32 of = koff + pr*(16*KST*2) + kk*32;
    lds(B[0], sb + 2*TSZ + of);
    lds(B[1], sb + 3*TSZ + of);
    mma3(Sv[2*pr], Sv[2*pr+1], A, B);
   }
  }

  float mx[2] = {-1e30f, -1e30f};
#pragma unroll
  for (int j = 0; j < 4; j++) {
   Sv[j][0] *= sf; Sv[j][1] *= sf; Sv[j][2] *= sf; Sv[j][3] *= sf;
   mx[0] = fmaxf(mx[0], fmaxf(Sv[j][0], Sv[j][1]));
   mx[1] = fmaxf(mx[1], fmaxf(Sv[j][2], Sv[j][3]));
  }
#pragma unroll
  for (int h = 0; h < 2; h++) {
   mx[h] = fmaxf(mx[h], __shfl_xor_sync(~0u, mx[h], 1));
   mx[h] = fmaxf(mx[h], __shfl_xor_sync(~0u, mx[h], 2));
   if (t == 0) sMx[nb*64 + rr[h]] = mx[h];
  }
  __syncthreads();

  const int par = kt & 1;
  float mn[2], sc[2], rs[2];
#pragma unroll
  for (int h = 0; h < 2; h++) {
   float mp = sM[par*64 + rr[h]];
   mn[h] = fmaxf(mp, fmaxf(sMx[rr[h]], sMx[64 + rr[h]]));
   sc[h] = __expf(mp - mn[h]);
   rs[h] = 0.f;
  }
#pragma unroll
  for (int j = 0; j < 4; j++) {
#pragma unroll
   for (int h = 0; h < 2; h++) {
    float pa = __expf(Sv[j][2*h] - mn[h]);
    float pb = __expf(Sv[j][2*h+1] - mn[h]);
    rs[h] += pa + pb;
    bf2 hv, lv; sp2(pa, pb, hv, lv);
    u32 po = (rr[h]*PST + nb*32 + j*8 + 2*t)*2;
    *(bf2*)(sm + SMP + po) = hv;
    *(bf2*)(sm + SMP + PSZ + po) = lv;
   }
  }
#pragma unroll
  for (int h = 0; h < 2; h++) {
   rs[h] += __shfl_xor_sync(~0u, rs[h], 1);
   rs[h] += __shfl_xor_sync(~0u, rs[h], 2);
   if (t == 0) {
    sL[nb*64 + rr[h]] = sL[nb*64 + rr[h]]*sc[h] + rs[h];
    if (nb == 0) sM[(par^1)*64 + rr[h]] = mn[h];
   }
  }
#pragma unroll
  for (int j = 0; j < 16; j++) {
   O[j][0] *= sc[0]; O[j][1] *= sc[0]; O[j][2] *= sc[1]; O[j][3] *= sc[1];
  }
  __syncthreads();
#pragma unroll
  for (int ks = 0; ks < 4; ks++) {
   u32 P[2][4];
   lds(P[0], sb + SMP + poff + ks*32);
   lds(P[1], sb + SMP + PSZ + poff + ks*32);
#pragma unroll
   for (int pr = 0; pr < 8; pr++) {
    u32 Vf[2][4];
    u32 of = voff + ks*(16*KST*2) + pr*32;
    ldt(Vf[0], sb + 4*TSZ + of);
    ldt(Vf[1], sb + 5*TSZ + of);
    mma3(O[2*pr], O[2*pr+1], P, Vf);
   }
  }
  __syncthreads();
 }

 float i0 = 1.f/(sL[rr[0]] + sL[64 + rr[0]]);
 float i1 = 1.f/(sL[rr[1]] + sL[64 + rr[1]]);
#pragma unroll
 for (int j = 0; j < 16; j++) {
  size_t oa = (size_t)(b*SS + q0 + rr[0])*DD + nb*128 + j*8 + 2*t;
  size_t ob = (size_t)(b*SS + q0 + rr[1])*DD + nb*128 + j*8 + 2*t;
  *(float2*)&out[oa] = make_float2(O[j][0]*i0, O[j][1]*i0);
  *(float2*)&out[ob] = make_float2(O[j][2]*i1, O[j][3]*i1);
 }
}

extern "C" void kernel_launch(void* const* d_in, const int* in_sizes, int n_in,
                              void* d_out, int out_size) {
 cudaFuncSetAttribute(attn, cudaFuncAttributeMaxDynamicSharedMemorySize, SMT);
 proj<<<(BB*SS)/64, 256>>>((const float*)d_in[0], (const float*)d_in[3],
                           (const float*)d_in[4], 0);
 proj<<<(BB*SS)/64, 256>>>((const float*)d_in[1], (const float*)d_in[5],
                           (const float*)d_in[6], 1);
 attn<<<BB*(SS/64), 256, SMT>>>((const float*)d_in[2], (const float*)d_in[7],
                                (float*)d_out);
}

// round 10
// speedup vs baseline: 2.0864x; 1.0132x over previous
#include <cuda_runtime.h>
#include <cuda_bf16.h>
#include <cstdint>
#define BB 4
#define SS 4096
#define DIN 512
#define DD 256
#define KST 264
#define PST 72
#define TSZ 33792
#define PSZ 9216
#define SMP 202752
#define SMR 221184
#define SMT 223744
typedef __nv_bfloat162 bf2;
typedef uint32_t u32;

__device__ __nv_bfloat16 gQ[2][BB*SS*DD], gK[2][BB*SS*DD];

__device__ __forceinline__ void sp2(float a, float b, bf2& h, bf2& l) {
 h.x = __float2bfloat16(a); h.y = __float2bfloat16(b);
 l.x = __float2bfloat16(a - __bfloat162float(h.x));
 l.y = __float2bfloat16(b - __bfloat162float(h.y));
}

__global__ __launch_bounds__(256, 2)
void proj(const float* __restrict__ X, const float* __restrict__ W,
          const float* __restrict__ bias, int dst) {
 __shared__ float sX[64*36], sW[256*36];
 const int tid = threadIdx.x, row0 = blockIdx.x*64;
 const int r0 = tid & 31, r1 = r0 + 32, c0 = (tid >> 5)*32;
 float a0[32], a1[32];
#pragma unroll
 for (int c = 0; c < 32; c++) { a0[c] = bias[c0+c]; a1[c] = a0[c]; }
 for (int i0 = 0; i0 < DIN; i0 += 32) {
#pragma unroll
  for (int u = tid; u < 512; u += 256)
   *(float4*)&sX[(u>>3)*36+(u&7)*4] = *(const float4*)&X[(row0+(u>>3))*DIN+i0+(u&7)*4];
#pragma unroll
  for (int u = tid; u < 2048; u += 256)
   *(float4*)&sW[(u>>3)*36+(u&7)*4] = *(const float4*)&W[(u>>3)*DIN+i0+(u&7)*4];
  __syncthreads();
#pragma unroll
  for (int ii = 0; ii < 32; ii += 4) {
   float4 xa = *(const float4*)&sX[r0*36+ii];
   float4 xb = *(const float4*)&sX[r1*36+ii];
#pragma unroll
   for (int c = 0; c < 32; c++) {
    float4 w = *(const float4*)&sW[(c0+c)*36+ii];
    a0[c] += xa.x*w.x + xa.y*w.y + xa.z*w.z + xa.w*w.w;
    a1[c] += xb.x*w.x + xb.y*w.y + xb.z*w.z + xb.w*w.w;
   }
  }
  __syncthreads();
 }
 __nv_bfloat16* oh = dst ? gK[0] : gQ[0];
 __nv_bfloat16* ol = dst ? gK[1] : gQ[1];
#pragma unroll
 for (int c = 0; c < 32; c += 2) {
  bf2 h, l;
  size_t oa = (size_t)(row0+r0)*DD + c0 + c, ob = (size_t)(row0+r1)*DD + c0 + c;
  sp2(a0[c], a0[c+1], h, l);
  *(bf2*)&oh[oa] = h; *(bf2*)&ol[oa] = l;
  sp2(a1[c], a1[c+1], h, l);
  *(bf2*)&oh[ob] = h; *(bf2*)&ol[ob] = l;
 }
}

__device__ __forceinline__ void lds(u32* r, u32 a) {
 asm volatile("ldmatrix.sync.aligned.m8n8.x4.shared.b16 {%0,%1,%2,%3},[%4];"
  : "=r"(r[0]), "=r"(r[1]), "=r"(r[2]), "=r"(r[3]) : "r"(a));
}
__device__ __forceinline__ void ldt(u32* r, u32 a) {
 asm volatile("ldmatrix.sync.aligned.m8n8.x4.trans.shared.b16 {%0,%1,%2,%3},[%4];"
  : "=r"(r[0]), "=r"(r[1]), "=r"(r[2]), "=r"(r[3]) : "r"(a));
}
__device__ __forceinline__ void mma(float* c, const u32* a, u32 b0, u32 b1) {
 asm volatile("mma.sync.aligned.m16n8k16.row.col.f32.bf16.bf16.f32 "
  "{%0,%1,%2,%3},{%4,%5,%6,%7},{%8,%9},{%0,%1,%2,%3};"
  : "+f"(c[0]), "+f"(c[1]), "+f"(c[2]), "+f"(c[3])
  : "r"(a[0]), "r"(a[1]), "r"(a[2]), "r"(a[3]), "r"(b0), "r"(b1));
}
__device__ __forceinline__ void mma3(float* cA, float* cB, u32 (*A)[4], u32 (*B)[4]) {
 mma(cA, A[0], B[0][0], B[0][1]); mma(cB, A[0], B[0][2], B[0][3]);
 mma(cA, A[0], B[1][0], B[1][1]); mma(cB, A[0], B[1][2], B[1][3]);
 mma(cA, A[1], B[0][0], B[0][1]); mma(cB, A[1], B[0][2], B[0][3]);
}

__global__ __launch_bounds__(512, 1)
void attn(const float* __restrict__ val, const float* __restrict__ sfp,
          float* __restrict__ out) {
 extern __shared__ char sm[];
 const u32 sb = (u32)__cvta_generic_to_shared(sm);
 float* sMx = (float*)(sm + SMR);      // [4][64]
 float* sM = sMx + 256;                // [2][64]
 float* sL = sMx + 384;                // [4][64]
 const int tid = threadIdx.x, lane = tid & 31, wid = tid >> 5;
 const int mb = wid & 3, nb = wid >> 2, t = lane & 3;
 const int b = blockIdx.x >> 6, q0 = (blockIdx.x & 63)*64;
 const float sf = *sfp;

 for (int u = tid; u < 2048; u += 512) {
  int r = u >> 5, c = u & 31;
  size_t gi = (size_t)(b*SS + q0 + r)*DD;
  u32 so = (r*KST + c*8)*2;
  *(uint4*)(sm + so) = ((const uint4*)(gQ[0] + gi))[c];
  *(uint4*)(sm + TSZ + so) = ((const uint4*)(gQ[1] + gi))[c];
 }
 if (tid < 128) sM[tid] = -1e30f;
 if (tid < 256) sL[tid] = 0.f;

 const int lr = lane & 7, qd = lane >> 3;
 const u32 aoff = ((mb*16 + (lane&15))*KST + (lane>>4)*8)*2;
 const u32 koff = ((nb*16 + (qd>>1)*8 + lr)*KST + (qd&1)*8)*2;
 const u32 voff = (((qd&1)*8 + lr)*KST + nb*64 + (qd>>1)*8)*2;
 const u32 poff = ((mb*16 + (lane&15))*PST + (lane>>4)*8)*2;

 float O[8][4];
#pragma unroll
 for (int j = 0; j < 8; j++) O[j][0] = O[j][1] = O[j][2] = O[j][3] = 0.f;
 int rr[2]; rr[0] = mb*16 + (lane >> 2); rr[1] = rr[0] + 8;

 for (int kt = 0; kt < SS/64; kt++) {
  for (int u = tid; u < 2048; u += 512) {
   int r = u >> 5, c = u & 31;
   size_t gi = (size_t)(b*SS + kt*64 + r)*DD;
   u32 so = (r*KST + c*8)*2;
   *(uint4*)(sm + 2*TSZ + so) = ((const uint4*)(gK[0] + gi))[c];
   *(uint4*)(sm + 3*TSZ + so) = ((const uint4*)(gK[1] + gi))[c];
  }
  for (int u = tid; u < 4096; u += 512) {
   int r = u >> 6, c = u & 63;
   float4 v = ((const float4*)&val[(size_t)(b*SS + kt*64 + r)*DD])[c];
   bf2 ha, la, hb, lb;
   sp2(v.x, v.y, ha, la); sp2(v.z, v.w, hb, lb);
   u32 so = (r*KST + c*4)*2;
   *(bf2*)(sm + 4*TSZ + so) = ha; *(bf2*)(sm + 4*TSZ + so + 4) = hb;
   *(bf2*)(sm + 5*TSZ + so) = la; *(bf2*)(sm + 5*TSZ + so + 4) = lb;
  }
  __syncthreads();

  float Sv[2][4];
#pragma unroll
  for (int j = 0; j < 2; j++) Sv[j][0] = Sv[j][1] = Sv[j][2] = Sv[j][3] = 0.f;
#pragma unroll 4
  for (int kk = 0; kk < 16; kk++) {
   u32 A[2][4], B[2][4];
   lds(A[0], sb + aoff + kk*32);
   lds(A[1], sb + TSZ + aoff + kk*32);
   u32 of = koff + kk*32;
   lds(B[0], sb + 2*TSZ + of);
   lds(B[1], sb + 3*TSZ + of);
   mma3(Sv[0], Sv[1], A, B);
  }

  float mx[2] = {-1e30f, -1e30f};
#pragma unroll
  for (int j = 0; j < 2; j++) {
   Sv[j][0] *= sf; Sv[j][1] *= sf; Sv[j][2] *= sf; Sv[j][3] *= sf;
   mx[0] = fmaxf(mx[0], fmaxf(Sv[j][0], Sv[j][1]));
   mx[1] = fmaxf(mx[1], fmaxf(Sv[j][2], Sv[j][3]));
  }
#pragma unroll
  for (int h = 0; h < 2; h++) {
   mx[h] = fmaxf(mx[h], __shfl_xor_sync(~0u, mx[h], 1));
   mx[h] = fmaxf(mx[h], __shfl_xor_sync(~0u, mx[h], 2));
   if (t == 0) sMx[nb*64 + rr[h]] = mx[h];
  }
  __syncthreads();

  const int par = kt & 1;
  float mn[2], sc[2], rs[2];
#pragma unroll
  for (int h = 0; h < 2; h++) {
   float mp = sM[par*64 + rr[h]];
   mn[h] = fmaxf(fmaxf(mp, fmaxf(sMx[rr[h]], sMx[64 + rr[h]])),
                 fmaxf(sMx[128 + rr[h]], sMx[192 + rr[h]]));
   sc[h] = __expf(mp - mn[h]);
   rs[h] = 0.f;
  }
#pragma unroll
  for (int j = 0; j < 2; j++) {
#pragma unroll
   for (int h = 0; h < 2; h++) {
    float pa = __expf(Sv[j][2*h] - mn[h]);
    float pb = __expf(Sv[j][2*h+1] - mn[h]);
    rs[h] += pa + pb;
    bf2 hv, lv; sp2(pa, pb, hv, lv);
    u32 po = (rr[h]*PST + nb*16 + j*8 + 2*t)*2;
    *(bf2*)(sm + SMP + po) = hv;
    *(bf2*)(sm + SMP + PSZ + po) = lv;
   }
  }
#pragma unroll
  for (int h = 0; h < 2; h++) {
   rs[h] += __shfl_xor_sync(~0u, rs[h], 1);
   rs[h] += __shfl_xor_sync(~0u, rs[h], 2);
   if (t == 0) {
    sL[nb*64 + rr[h]] = sL[nb*64 + rr[h]]*sc[h] + rs[h];
    if (nb == 0) sM[(par^1)*64 + rr[h]] = mn[h];
   }
  }
#pragma unroll
  for (int j = 0; j < 8; j++) {
   O[j][0] *= sc[0]; O[j][1] *= sc[0]; O[j][2] *= sc[1]; O[j][3] *= sc[1];
  }
  __syncthreads();
#pragma unroll
  for (int ks = 0; ks < 4; ks++) {
   u32 P[2][4];
   lds(P[0], sb + SMP + poff + ks*32);
   lds(P[1], sb + SMP + PSZ + poff + ks*32);
#pragma unroll
   for (int pr = 0; pr < 4; pr++) {
    u32 Vf[2][4];
    u32 of = voff + ks*(16*KST*2) + pr*32;
    ldt(Vf[0], sb + 4*TSZ + of);
    ldt(Vf[1], sb + 5*TSZ + of);
    mma3(O[2*pr], O[2*pr+1], P, Vf);
   }
  }
  __syncthreads();
 }

 float i0 = 1.f/(sL[rr[0]] + sL[64+rr[0]] + sL[128+rr[0]] + sL[192+rr[0]]);
 float i1 = 1.f/(sL[rr[1]] + sL[64+rr[1]] + sL[128+rr[1]] + sL[192+rr[1]]);
#pragma unroll
 for (int j = 0; j < 8; j++) {
  size_t oa = (size_t)(b*SS + q0 + rr[0])*DD + nb*64 + j*8 + 2*t;
  size_t ob = (size_t)(b*SS + q0 + rr[1])*DD + nb*64 + j*8 + 2*t;
  *(float2*)&out[oa] = make_float2(O[j][0]*i0, O[j][1]*i0);
  *(float2*)&out[ob] = make_float2(O[j][2]*i1, O[j][3]*i1);
 }
}

extern "C" void kernel_launch(void* const* d_in, const int* in_sizes, int n_in,
                              void* d_out, int out_size) {
 cudaFuncSetAttribute(attn, cudaFuncAttributeMaxDynamicSharedMemorySize, SMT);
 proj<<<(BB*SS)/64, 256>>>((const float*)d_in[0], (const float*)d_in[3],
                           (const float*)d_in[4], 0);
 proj<<<(BB*SS)/64, 256>>>((const float*)d_in[1], (const float*)d_in[5],
                           (const float*)d_in[6], 1);
 attn<<<BB*(SS/64), 512, SMT>>>((const float*)d_in[2], (const float*)d_in[7],
                                (float*)d_out);
}

// round 11
// speedup vs baseline: 2.4181x; 1.1590x over previous
#include <cuda_runtime.h>
#include <cuda_bf16.h>
#include <cstdint>
#define BB 4
#define SS 4096
#define DIN 512
#define DD 256
#define KST 264
#define PST 72
#define WST 72
#define TSZ 33792
#define PSZ 9216
#define SMP 202752
#define SMR 221184
#define SMT 223744
typedef __nv_bfloat162 bf2;
typedef uint32_t u32;

__device__ __nv_bfloat16 gQ[2][BB*SS*DD], gK[2][BB*SS*DD];
__device__ __nv_bfloat16 gXQ[2][BB*SS*DIN], gXK[2][BB*SS*DIN];
__device__ __nv_bfloat16 gWQ[2][DD*DIN], gWK[2][DD*DIN];

__device__ __forceinline__ void sp2(float a, float b, bf2& h, bf2& l) {
 h.x = __float2bfloat16(a); h.y = __float2bfloat16(b);
 l.x = __float2bfloat16(a - __bfloat162float(h.x));
 l.y = __float2bfloat16(b - __bfloat162float(h.y));
}

__global__ void splitk(const float* __restrict__ in, int which) {
 __nv_bfloat16* oh = which==0 ? gXQ[0] : which==1 ? gXK[0] : which==2 ? gWQ[0] : gWK[0];
 __nv_bfloat16* ol = which==0 ? gXQ[1] : which==1 ? gXK[1] : which==2 ? gWQ[1] : gWK[1];
 int i = (blockIdx.x*256 + threadIdx.x)*2;
 float2 v = *(const float2*)&in[i];
 bf2 h, l; sp2(v.x, v.y, h, l);
 *(bf2*)&oh[i] = h; *(bf2*)&ol[i] = l;
}

__device__ __forceinline__ void lds(u32* r, u32 a) {
 asm volatile("ldmatrix.sync.aligned.m8n8.x4.shared.b16 {%0,%1,%2,%3},[%4];"
  : "=r"(r[0]), "=r"(r[1]), "=r"(r[2]), "=r"(r[3]) : "r"(a));
}
__device__ __forceinline__ void ldt(u32* r, u32 a) {
 asm volatile("ldmatrix.sync.aligned.m8n8.x4.trans.shared.b16 {%0,%1,%2,%3},[%4];"
  : "=r"(r[0]), "=r"(r[1]), "=r"(r[2]), "=r"(r[3]) : "r"(a));
}
__device__ __forceinline__ void mma(float* c, const u32* a, u32 b0, u32 b1) {
 asm volatile("mma.sync.aligned.m16n8k16.row.col.f32.bf16.bf16.f32 "
  "{%0,%1,%2,%3},{%4,%5,%6,%7},{%8,%9},{%0,%1,%2,%3};"
  : "+f"(c[0]), "+f"(c[1]), "+f"(c[2]), "+f"(c[3])
  : "r"(a[0]), "r"(a[1]), "r"(a[2]), "r"(a[3]), "r"(b0), "r"(b1));
}
__device__ __forceinline__ void mma3(float* cA, float* cB, u32 (*A)[4], u32 (*B)[4]) {
 mma(cA, A[0], B[0][0], B[0][1]); mma(cB, A[0], B[0][2], B[0][3]);
 mma(cA, A[0], B[1][0], B[1][1]); mma(cB, A[0], B[1][2], B[1][3]);
 mma(cA, A[1], B[0][0], B[0][1]); mma(cB, A[1], B[0][2], B[0][3]);
}

// one launch computes both projections: CTA 64 rows x 256 cols, K chunked by 64
__global__ __launch_bounds__(256, 2)
void pmma(const float* __restrict__ bq, const float* __restrict__ bk) {
 extern __shared__ char ps[];
 const u32 sb = (u32)__cvta_generic_to_shared(ps);
 const int tid = threadIdx.x, lane = tid & 31, wid = tid >> 5;
 const int mb = wid & 3, nb = wid >> 2, t = lane & 3;
 const int dst = blockIdx.x >= 256;
 const int row0 = (blockIdx.x & 255)*64;
 const __nv_bfloat16* Xp[2] = { dst ? gXK[0] : gXQ[0], dst ? gXK[1] : gXQ[1] };
 const __nv_bfloat16* Wp[2] = { dst ? gWK[0] : gWQ[0], dst ? gWK[1] : gWQ[1] };
 const float* bias = dst ? bk : bq;

 const int lr = lane & 7, qd = lane >> 3;
 const u32 aoff = ((mb*16 + (lane&15))*WST + (lane>>4)*8)*2;
 const u32 boff = ((nb*128 + (qd>>1)*8 + lr)*WST + (qd&1)*8)*2;
 // smem: XA hi 0, XA lo 9216, WB hi 18432, WB lo 55296
 float O[16][4];
#pragma unroll
 for (int j = 0; j < 16; j++) O[j][0] = O[j][1] = O[j][2] = O[j][3] = 0.f;

 for (int kc = 0; kc < 8; kc++) {
#pragma unroll
  for (int u = tid; u < 512; u += 256) {
   int r = u >> 3, c8 = u & 7;
   size_t gi = (size_t)(row0 + r)*DIN + kc*64 + c8*8;
   u32 so = (r*WST + c8*8)*2;
   *(uint4*)(ps + so) = *(const uint4*)(Xp[0] + gi);
   *(uint4*)(ps + 9216 + so) = *(const uint4*)(Xp[1] + gi);
  }
#pragma unroll
  for (int u = tid; u < 2048; u += 256) {
   int r = u >> 3, c8 = u & 7;
   size_t gi = (size_t)r*DIN + kc*64 + c8*8;
   u32 so = (r*WST + c8*8)*2;
   *(uint4*)(ps + 18432 + so) = *(const uint4*)(Wp[0] + gi);
   *(uint4*)(ps + 55296 + so) = *(const uint4*)(Wp[1] + gi);
  }
  __syncthreads();
#pragma unroll
  for (int kk = 0; kk < 4; kk++) {
   u32 A[2][4];
   lds(A[0], sb + aoff + kk*32);
   lds(A[1], sb + 9216 + aoff + kk*32);
#pragma unroll
   for (int pr = 0; pr < 8; pr++) {
    u32 B[2][4];
    u32 of = boff + pr*(16*WST*2) + kk*32;
    lds(B[0], sb + 18432 + of);
    lds(B[1], sb + 55296 + of);
    mma3(O[2*pr], O[2*pr+1], A, B);
   }
  }
  __syncthreads();
 }
 __nv_bfloat16* oh = dst ? gK[0] : gQ[0];
 __nv_bfloat16* ol = dst ? gK[1] : gQ[1];
 const int r0 = mb*16 + (lane >> 2), r1 = r0 + 8;
#pragma unroll
 for (int j = 0; j < 16; j++) {
  int n0 = nb*128 + j*8 + 2*t;
  float2 bv = *(const float2*)&bias[n0];
  bf2 h, l;
  sp2(O[j][0] + bv.x, O[j][1] + bv.y, h, l);
  *(bf2*)&oh[(size_t)(row0+r0)*DD + n0] = h;
  *(bf2*)&ol[(size_t)(row0+r0)*DD + n0] = l;
  sp2(O[j][2] + bv.x, O[j][3] + bv.y, h, l);
  *(bf2*)&oh[(size_t)(row0+r1)*DD + n0] = h;
  *(bf2*)&ol[(size_t)(row0+r1)*DD + n0] = l;
 }
}

__global__ __launch_bounds__(512, 1)
void attn(const float* __restrict__ val, const float* __restrict__ sfp,
          float* __restrict__ out) {
 extern __shared__ char sm[];
 const u32 sb = (u32)__cvta_generic_to_shared(sm);
 float* sMx = (float*)(sm + SMR);
 float* sM = sMx + 256;
 float* sL = sMx + 384;
 const int tid = threadIdx.x, lane = tid & 31, wid = tid >> 5;
 const int mb = wid & 3, nb = wid >> 2, t = lane & 3;
 const int b = blockIdx.x >> 6, q0 = (blockIdx.x & 63)*64;
 const float sf = *sfp;

 for (int u = tid; u < 2048; u += 512) {
  int r = u >> 5, c = u & 31;
  size_t gi = (size_t)(b*SS + q0 + r)*DD;
  u32 so = (r*KST + c*8)*2;
  *(uint4*)(sm + so) = ((const uint4*)(gQ[0] + gi))[c];
  *(uint4*)(sm + TSZ + so) = ((const uint4*)(gQ[1] + gi))[c];
 }
 if (tid < 128) sM[tid] = -1e30f;
 if (tid < 256) sL[tid] = 0.f;

 const int lr = lane & 7, qd = lane >> 3;
 const u32 aoff = ((mb*16 + (lane&15))*KST + (lane>>4)*8)*2;
 const u32 koff = ((nb*16 + (qd>>1)*8 + lr)*KST + (qd&1)*8)*2;
 const u32 voff = (((qd&1)*8 + lr)*KST + nb*64 + (qd>>1)*8)*2;
 const u32 poff = ((mb*16 + (lane&15))*PST + (lane>>4)*8)*2;

 float O[8][4];
#pragma unroll
 for (int j = 0; j < 8; j++) O[j][0] = O[j][1] = O[j][2] = O[j][3] = 0.f;
 int rr[2]; rr[0] = mb*16 + (lane >> 2); rr[1] = rr[0] + 8;

 for (int kt = 0; kt < SS/64; kt++) {
  for (int u = tid; u < 2048; u += 512) {
   int r = u >> 5, c = u & 31;
   size_t gi = (size_t)(b*SS + kt*64 + r)*DD;
   u32 so = (r*KST + c*8)*2;
   *(uint4*)(sm + 2*TSZ + so) = ((const uint4*)(gK[0] + gi))[c];
   *(uint4*)(sm + 3*TSZ + so) = ((const uint4*)(gK[1] + gi))[c];
  }
  for (int u = tid; u < 4096; u += 512) {
   int r = u >> 6, c = u & 63;
   float4 v = ((const float4*)&val[(size_t)(b*SS + kt*64 + r)*DD])[c];
   bf2 ha, la, hb, lb;
   sp2(v.x, v.y, ha, la); sp2(v.z, v.w, hb, lb);
   u32 so = (r*KST + c*4)*2;
   *(bf2*)(sm + 4*TSZ + so) = ha; *(bf2*)(sm + 4*TSZ + so + 4) = hb;
   *(bf2*)(sm + 5*TSZ + so) = la; *(bf2*)(sm + 5*TSZ + so + 4) = lb;
  }
  __syncthreads();

  float Sv[2][4];
#pragma unroll
  for (int j = 0; j < 2; j++) Sv[j][0] = Sv[j][1] = Sv[j][2] = Sv[j][3] = 0.f;
#pragma unroll 4
  for (int kk = 0; kk < 16; kk++) {
   u32 A[2][4], B[2][4];
   lds(A[0], sb + aoff + kk*32);
   lds(A[1], sb + TSZ + aoff + kk*32);
   u32 of = koff + kk*32;
   lds(B[0], sb + 2*TSZ + of);
   lds(B[1], sb + 3*TSZ + of);
   mma3(Sv[0], Sv[1], A, B);
  }

  float mx[2] = {-1e30f, -1e30f};
#pragma unroll
  for (int j = 0; j < 2; j++) {
   Sv[j][0] *= sf; Sv[j][1] *= sf; Sv[j][2] *= sf; Sv[j][3] *= sf;
   mx[0] = fmaxf(mx[0], fmaxf(Sv[j][0], Sv[j][1]));
   mx[1] = fmaxf(mx[1], fmaxf(Sv[j][2], Sv[j][3]));
  }
#pragma unroll
  for (int h = 0; h < 2; h++) {
   mx[h] = fmaxf(mx[h], __shfl_xor_sync(~0u, mx[h], 1));
   mx[h] = fmaxf(mx[h], __shfl_xor_sync(~0u, mx[h], 2));
   if (t == 0) sMx[nb*64 + rr[h]] = mx[h];
  }
  __syncthreads();

  const int par = kt & 1;
  float mn[2], sc[2], rs[2];
#pragma unroll
  for (int h = 0; h < 2; h++) {
   float mp = sM[par*64 + rr[h]];
   mn[h] = fmaxf(fmaxf(mp, fmaxf(sMx[rr[h]], sMx[64 + rr[h]])),
                 fmaxf(sMx[128 + rr[h]], sMx[192 + rr[h]]));
   sc[h] = __expf(mp - mn[h]);
   rs[h] = 0.f;
  }
#pragma unroll
  for (int j = 0; j < 2; j++) {
#pragma unroll
   for (int h = 0; h < 2; h++) {
    float pa = __expf(Sv[j][2*h] - mn[h]);
    float pb = __expf(Sv[j][2*h+1] - mn[h]);
    rs[h] += pa + pb;
    bf2 hv, lv; sp2(pa, pb, hv, lv);
    u32 po = (rr[h]*PST + nb*16 + j*8 + 2*t)*2;
    *(bf2*)(sm + SMP + po) = hv;
    *(bf2*)(sm + SMP + PSZ + po) = lv;
   }
  }
#pragma unroll
  for (int h = 0; h < 2; h++) {
   rs[h] += __shfl_xor_sync(~0u, rs[h], 1);
   rs[h] += __shfl_xor_sync(~0u, rs[h], 2);
   if (t == 0) {
    sL[nb*64 + rr[h]] = sL[nb*64 + rr[h]]*sc[h] + rs[h];
    if (nb == 0) sM[(par^1)*64 + rr[h]] = mn[h];
   }
  }
#pragma unroll
  for (int j = 0; j < 8; j++) {
   O[j][0] *= sc[0]; O[j][1] *= sc[0]; O[j][2] *= sc[1]; O[j][3] *= sc[1];
  }
  __syncthreads();
#pragma unroll
  for (int ks = 0; ks < 4; ks++) {
   u32 P[2][4];
   lds(P[0], sb + SMP + poff + ks*32);
   lds(P[1], sb + SMP + PSZ + poff + ks*32);
#pragma unroll
   for (int pr = 0; pr < 4; pr++) {
    u32 Vf[2][4];
    u32 of = voff + ks*(16*KST*2) + pr*32;
    ldt(Vf[0], sb + 4*TSZ + of);
    ldt(Vf[1], sb + 5*TSZ + of);
    mma3(O[2*pr], O[2*pr+1], P, Vf);
   }
  }
  __syncthreads();
 }

 float i0 = 1.f/(sL[rr[0]] + sL[64+rr[0]] + sL[128+rr[0]] + sL[192+rr[0]]);
 float i1 = 1.f/(sL[rr[1]] + sL[64+rr[1]] + sL[128+rr[1]] + sL[192+rr[1]]);
#pragma unroll
 for (int j = 0; j < 8; j++) {
  size_t oa = (size_t)(b*SS + q0 + rr[0])*DD + nb*64 + j*8 + 2*t;
  size_t ob = (size_t)(b*SS + q0 + rr[1])*DD + nb*64 + j*8 + 2*t;
  *(float2*)&out[oa] = make_float2(O[j][0]*i0, O[j][1]*i0);
  *(float2*)&out[ob] = make_float2(O[j][2]*i1, O[j][3]*i1);
 }
}

extern "C" void kernel_launch(void* const* d_in, const int* in_sizes, int n_in,
                              void* d_out, int out_size) {
 cudaFuncSetAttribute(attn, cudaFuncAttributeMaxDynamicSharedMemorySize, SMT);
 cudaFuncSetAttribute(pmma, cudaFuncAttributeMaxDynamicSharedMemorySize, 92160);
 splitk<<<(BB*SS*DIN)/512, 256>>>((const float*)d_in[0], 0);
 splitk<<<(BB*SS*DIN)/512, 256>>>((const float*)d_in[1], 1);
 splitk<<<(DD*DIN)/512, 256>>>((const float*)d_in[3], 2);
 splitk<<<(DD*DIN)/512, 256>>>((const float*)d_in[5], 3);
 pmma<<<512, 256, 92160>>>((const float*)d_in[4], (const float*)d_in[6]);
 attn<<<BB*(SS/64), 512, SMT>>>((const float*)d_in[2], (const float*)d_in[7],
                                (float*)d_out);
}

// round 13
// speedup vs baseline: 2.8732x; 1.1882x over previous
#include <cuda_runtime.h>
#include <cuda_bf16.h>
#include <cuda_fp16.h>
#include <cstdint>
#define BB 4
#define SS 4096
#define DIN 512
#define DD 256
#define KST 264
#define PST 72
#define WST 72
#define TSZ 33792
#define SMP 202752
#define SMR 221184
#define SMT 223744
typedef __nv_bfloat162 bf2;
typedef uint32_t u32;

__device__ __nv_bfloat16 gQ[2][BB*SS*DD], gK[2][BB*SS*DD];
__device__ __nv_bfloat16 gXQ[2][BB*SS*DIN], gXK[2][BB*SS*DIN];
__device__ __nv_bfloat16 gWQ[2][DD*DIN], gWK[2][DD*DIN];

__device__ __forceinline__ void sp2(float a, float b, bf2& h, bf2& l) {
 h.x = __float2bfloat16(a); h.y = __float2bfloat16(b);
 l.x = __float2bfloat16(a - __bfloat162float(h.x));
 l.y = __float2bfloat16(b - __bfloat162float(h.y));
}

__global__ void splitk(const float* __restrict__ in, int w) {
 __nv_bfloat16* oh = w==0 ? gXQ[0] : w==1 ? gXK[0] : w==2 ? gWQ[0] : gWK[0];
 __nv_bfloat16* ol = w==0 ? gXQ[1] : w==1 ? gXK[1] : w==2 ? gWQ[1] : gWK[1];
 int i = (blockIdx.x*256 + threadIdx.x)*2;
 float2 v = *(const float2*)&in[i];
 bf2 h, l; sp2(v.x, v.y, h, l);
 *(bf2*)&oh[i] = h; *(bf2*)&ol[i] = l;
}

__device__ __forceinline__ void lds(u32* r, u32 a) {
 asm volatile("ldmatrix.sync.aligned.m8n8.x4.shared.b16 {%0,%1,%2,%3},[%4];"
  : "=r"(r[0]), "=r"(r[1]), "=r"(r[2]), "=r"(r[3]) : "r"(a));
}
__device__ __forceinline__ void ldt(u32* r, u32 a) {
 asm volatile("ldmatrix.sync.aligned.m8n8.x4.trans.shared.b16 {%0,%1,%2,%3},[%4];"
  : "=r"(r[0]), "=r"(r[1]), "=r"(r[2]), "=r"(r[3]) : "r"(a));
}
__device__ __forceinline__ void mma(float* c, const u32* a, u32 b0, u32 b1) {
 asm volatile("mma.sync.aligned.m16n8k16.row.col.f32.bf16.bf16.f32 "
  "{%0,%1,%2,%3},{%4,%5,%6,%7},{%8,%9},{%0,%1,%2,%3};"
  : "+f"(c[0]), "+f"(c[1]), "+f"(c[2]), "+f"(c[3])
  : "r"(a[0]), "r"(a[1]), "r"(a[2]), "r"(a[3]), "r"(b0), "r"(b1));
}
__device__ __forceinline__ void mmah(float* c, const u32* a, u32 b0, u32 b1) {
 asm volatile("mma.sync.aligned.m16n8k16.row.col.f32.f16.f16.f32 "
  "{%0,%1,%2,%3},{%4,%5,%6,%7},{%8,%9},{%0,%1,%2,%3};"
  : "+f"(c[0]), "+f"(c[1]), "+f"(c[2]), "+f"(c[3])
  : "r"(a[0]), "r"(a[1]), "r"(a[2]), "r"(a[3]), "r"(b0), "r"(b1));
}
__device__ __forceinline__ void mma3(float* cA, float* cB, u32 (*A)[4], u32 (*B)[4]) {
 mma(cA, A[0], B[0][0], B[0][1]); mma(cB, A[0], B[0][2], B[0][3]);
 mma(cA, A[0], B[1][0], B[1][1]); mma(cB, A[0], B[1][2], B[1][3]);
 mma(cA, A[1], B[0][0], B[0][1]); mma(cB, A[1], B[0][2], B[0][3]);
}

__global__ __launch_bounds__(256, 2)
void pmma(const float* __restrict__ bq, const float* __restrict__ bk) {
 extern __shared__ char ps[];
 const u32 sb = (u32)__cvta_generic_to_shared(ps);
 const int tid = threadIdx.x, lane = tid & 31, wid = tid >> 5;
 const int mb = wid & 3, nb = wid >> 2, t = lane & 3;
 const int dst = blockIdx.x >= 256;
 const int row0 = (blockIdx.x & 255)*64;
 const __nv_bfloat16* Xp[2] = { dst ? gXK[0] : gXQ[0], dst ? gXK[1] : gXQ[1] };
 const __nv_bfloat16* Wp[2] = { dst ? gWK[0] : gWQ[0], dst ? gWK[1] : gWQ[1] };
 const float* bias = dst ? bk : bq;
 const int lr = lane & 7, qd = lane >> 3;
 const u32 aoff = ((mb*16 + (lane&15))*WST + (lane>>4)*8)*2;
 const u32 boff = ((nb*128 + (qd>>1)*8 + lr)*WST + (qd&1)*8)*2;
 float O[16][4];
#pragma unroll
 for (int j = 0; j < 16; j++) O[j][0] = O[j][1] = O[j][2] = O[j][3] = 0.f;
 for (int kc = 0; kc < 8; kc++) {
#pragma unroll
  for (int u = tid; u < 512; u += 256) {
   int r = u >> 3, c8 = u & 7;
   size_t gi = (size_t)(row0 + r)*DIN + kc*64 + c8*8;
   u32 so = (r*WST + c8*8)*2;
   *(uint4*)(ps + so) = *(const uint4*)(Xp[0] + gi);
   *(uint4*)(ps + 9216 + so) = *(const uint4*)(Xp[1] + gi);
  }
#pragma unroll
  for (int u = tid; u < 2048; u += 256) {
   int r = u >> 3, c8 = u & 7;
   size_t gi = (size_t)r*DIN + kc*64 + c8*8;
   u32 so = (r*WST + c8*8)*2;
   *(uint4*)(ps + 18432 + so) = *(const uint4*)(Wp[0] + gi);
   *(uint4*)(ps + 55296 + so) = *(const uint4*)(Wp[1] + gi);
  }
  __syncthreads();
#pragma unroll
  for (int kk = 0; kk < 4; kk++) {
   u32 A[2][4];
   lds(A[0], sb + aoff + kk*32);
   lds(A[1], sb + 9216 + aoff + kk*32);
#pragma unroll
   for (int pr = 0; pr < 8; pr++) {
    u32 B[2][4];
    u32 of = boff + pr*(16*WST*2) + kk*32;
    lds(B[0], sb + 18432 + of);
    lds(B[1], sb + 55296 + of);
    mma3(O[2*pr], O[2*pr+1], A, B);
   }
  }
  __syncthreads();
 }
 __nv_bfloat16* oh = dst ? gK[0] : gQ[0];
 __nv_bfloat16* ol = dst ? gK[1] : gQ[1];
 const int r0 = mb*16 + (lane >> 2), r1 = r0 + 8;
#pragma unroll
 for (int j = 0; j < 16; j++) {
  int n0 = nb*128 + j*8 + 2*t;
  float2 bv = *(const float2*)&bias[n0];
  bf2 h, l;
  sp2(O[j][0] + bv.x, O[j][1] + bv.y, h, l);
  *(bf2*)&oh[(size_t)(row0+r0)*DD + n0] = h;
  *(bf2*)&ol[(size_t)(row0+r0)*DD + n0] = l;
  sp2(O[j][2] + bv.x, O[j][3] + bv.y, h, l);
  *(bf2*)&oh[(size_t)(row0+r1)*DD + n0] = h;
  *(bf2*)&ol[(size_t)(row0+r1)*DD + n0] = l;
 }
}

__global__ __launch_bounds__(512, 1)
void attn(const float* __restrict__ val, const float* __restrict__ sfp,
          float* __restrict__ out) {
 extern __shared__ char sm[];
 const u32 sb = (u32)__cvta_generic_to_shared(sm);
 float* sMx = (float*)(sm + SMR);
 float* sM = sMx + 256;
 float* sL = sMx + 384;
 const int tid = threadIdx.x, lane = tid & 31, wid = tid >> 5;
 const int mb = wid & 3, nb = wid >> 2, t = lane & 3;
 const int b = blockIdx.x >> 6, q0 = (blockIdx.x & 63)*64;
 const float sf = *sfp;

 for (int u = tid; u < 2048; u += 512) {
  int r = u >> 5, c = u & 31;
  size_t gi = (size_t)(b*SS + q0 + r)*DD;
  u32 so = (r*KST + c*8)*2;
  *(uint4*)(sm + so) = ((const uint4*)(gQ[0] + gi))[c];
  *(uint4*)(sm + TSZ + so) = ((const uint4*)(gQ[1] + gi))[c];
 }
 if (tid < 128) sM[tid] = -1e30f;
 if (tid < 256) sL[tid] = 0.f;

 const int lr = lane & 7, qd = lane >> 3;
 const u32 aoff = ((mb*16 + (lane&15))*KST + (lane>>4)*8)*2;
 const u32 koff = ((nb*16 + (qd>>1)*8 + lr)*KST + (qd&1)*8)*2;
 const u32 voff = (((qd&1)*8 + lr)*KST + nb*64 + (qd>>1)*8)*2;
 const u32 poff = ((mb*16 + (lane&15))*PST + (lane>>4)*8)*2;

 float O[8][4];
#pragma unroll
 for (int j = 0; j < 8; j++) O[j][0] = O[j][1] = O[j][2] = O[j][3] = 0.f;
 int rr[2]; rr[0] = mb*16 + (lane >> 2); rr[1] = rr[0] + 8;

 for (int kt = 0; kt < SS/64; kt++) {
  for (int u = tid; u < 2048; u += 512) {
   int r = u >> 5, c = u & 31;
   size_t gi = (size_t)(b*SS + kt*64 + r)*DD;
   u32 so = (r*KST + c*8)*2;
   *(uint4*)(sm + 2*TSZ + so) = ((const uint4*)(gK[0] + gi))[c];
   *(uint4*)(sm + 3*TSZ + so) = ((const uint4*)(gK[1] + gi))[c];
  }
  for (int u = tid; u < 4096; u += 512) {
   int r = u >> 6, c = u & 63;
   float4 v = ((const float4*)&val[(size_t)(b*SS + kt*64 + r)*DD])[c];
   __half2 va = __floats2half2_rn(v.x, v.y);
   __half2 vb = __floats2half2_rn(v.z, v.w);
   u32 so = (r*KST + c*4)*2;
   *(__half2*)(sm + 4*TSZ + so) = va;
   *(__half2*)(sm + 4*TSZ + so + 4) = vb;
  }
  __syncthreads();

  float Sv[2][4];
#pragma unroll
  for (int j = 0; j < 2; j++) Sv[j][0] = Sv[j][1] = Sv[j][2] = Sv[j][3] = 0.f;
#pragma unroll 4
  for (int kk = 0; kk < 16; kk++) {
   u32 A[2][4], B[2][4];
   lds(A[0], sb + aoff + kk*32);
   lds(A[1], sb + TSZ + aoff + kk*32);
   u32 of = koff + kk*32;
   lds(B[0], sb + 2*TSZ + of);
   lds(B[1], sb + 3*TSZ + of);
   mma3(Sv[0], Sv[1], A, B);
  }

  float mx[2] = {-1e30f, -1e30f};
#pragma unroll
  for (int j = 0; j < 2; j++) {
   Sv[j][0] *= sf; Sv[j][1] *= sf; Sv[j][2] *= sf; Sv[j][3] *= sf;
   mx[0] = fmaxf(mx[0], fmaxf(Sv[j][0], Sv[j][1]));
   mx[1] = fmaxf(mx[1], fmaxf(Sv[j][2], Sv[j][3]));
  }
#pragma unroll
  for (int h = 0; h < 2; h++) {
   mx[h] = fmaxf(mx[h], __shfl_xor_sync(~0u, mx[h], 1));
   mx[h] = fmaxf(mx[h], __shfl_xor_sync(~0u, mx[h], 2));
   if (t == 0) sMx[nb*64 + rr[h]] = mx[h];
  }
  __syncthreads();

  const int par = kt & 1;
  float mn[2], sc[2], rs[2];
#pragma unroll
  for (int h = 0; h < 2; h++) {
   float mp = sM[par*64 + rr[h]];
   mn[h] = fmaxf(fmaxf(mp, fmaxf(sMx[rr[h]], sMx[64 + rr[h]])),
                 fmaxf(sMx[128 + rr[h]], sMx[192 + rr[h]]));
   sc[h] = __expf(mp - mn[h]);
   rs[h] = 0.f;
  }
#pragma unroll
  for (int j = 0; j < 2; j++) {
#pragma unroll
   for (int h = 0; h < 2; h++) {
    float pa = __expf(Sv[j][2*h] - mn[h]);
    float pb = __expf(Sv[j][2*h+1] - mn[h]);
    rs[h] += pa + pb;
    u32 po = (rr[h]*PST + nb*16 + j*8 + 2*t)*2;
    *(__half2*)(sm + SMP + po) = __floats2half2_rn(pa, pb);
   }
  }
#pragma unroll
  for (int h = 0; h < 2; h++) {
   rs[h] += __shfl_xor_sync(~0u, rs[h], 1);
   rs[h] += __shfl_xor_sync(~0u, rs[h], 2);
   if (t == 0) {
    sL[nb*64 + rr[h]] = sL[nb*64 + rr[h]]*sc[h] + rs[h];
    if (nb == 0) sM[(par^1)*64 + rr[h]] = mn[h];
   }
  }
#pragma unroll
  for (int j = 0; j < 8; j++) {
   O[j][0] *= sc[0]; O[j][1] *= sc[0]; O[j][2] *= sc[1]; O[j][3] *= sc[1];
  }
  __syncthreads();
#pragma unroll
  for (int ks = 0; ks < 4; ks++) {
   u32 P1[4];
   lds(P1, sb + SMP + poff + ks*32);
#pragma unroll
   for (int pr = 0; pr < 4; pr++) {
    u32 Vf[4];
    ldt(Vf, sb + 4*TSZ + voff + ks*(16*KST*2) + pr*32);
    mmah(O[2*pr], P1, Vf[0], Vf[1]);
    mmah(O[2*pr+1], P1, Vf[2], Vf[3]);
   }
  }
  __syncthreads();
 }

 float i0 = 1.f/(sL[rr[0]] + sL[64+rr[0]] + sL[128+rr[0]] + sL[192+rr[0]]);
 float i1 = 1.f/(sL[rr[1]] + sL[64+rr[1]] + sL[128+rr[1]] + sL[192+rr[1]]);
#pragma unroll
 for (int j = 0; j < 8; j++) {
  size_t oa = (size_t)(b*SS + q0 + rr[0])*DD + nb*64 + j*8 + 2*t;
  size_t ob = (size_t)(b*SS + q0 + rr[1])*DD + nb*64 + j*8 + 2*t;
  *(float2*)&out[oa] = make_float2(O[j][0]*i0, O[j][1]*i0);
  *(float2*)&out[ob] = make_float2(O[j][2]*i1, O[j][3]*i1);
 }
}

extern "C" void kernel_launch(void* const* d_in, const int* in_sizes, int n_in,
                              void* d_out, int out_size) {
 cudaFuncSetAttribute(attn, cudaFuncAttributeMaxDynamicSharedMemorySize, SMT);
 cudaFuncSetAttribute(pmma, cudaFuncAttributeMaxDynamicSharedMemorySize, 92160);
 splitk<<<(BB*SS*DIN)/512, 256>>>((const float*)d_in[0], 0);
 splitk<<<(BB*SS*DIN)/512, 256>>>((const float*)d_in[1], 1);
 splitk<<<(DD*DIN)/512, 256>>>((const float*)d_in[3], 2);
 splitk<<<(DD*DIN)/512, 256>>>((const float*)d_in[5], 3);
 pmma<<<512, 256, 92160>>>((const float*)d_in[4], (const float*)d_in[6]);
 attn<<<BB*(SS/64), 512, SMT>>>((const float*)d_in[2], (const float*)d_in[7],
                                (float*)d_out);
}

// round 14
// speedup vs baseline: 3.1515x; 1.0969x over previous
#include <cuda_runtime.h>
#include <cuda_bf16.h>
#include <cuda_fp16.h>
#include <cstdint>
#define BB 4
#define SS 4096
#define DIN 512
#define DD 256
#define KST 264
#define PST 72
#define WST 72
#define TSZ 33792
#define SMP 135168
#define SMR 144384
#define SMT 146944
typedef __nv_bfloat162 bf2;
typedef uint32_t u32;

__device__ __half gQ[BB*SS*DD];
__device__ __half gK[2][BB*SS*DD];
__device__ __nv_bfloat16 gXQ[2][BB*SS*DIN], gXK[2][BB*SS*DIN];
__device__ __nv_bfloat16 gWQ[2][DD*DIN], gWK[2][DD*DIN];

__device__ __forceinline__ void sp2(float a, float b, bf2& h, bf2& l) {
 h.x = __float2bfloat16(a); h.y = __float2bfloat16(b);
 l.x = __float2bfloat16(a - __bfloat162float(h.x));
 l.y = __float2bfloat16(b - __bfloat162float(h.y));
}
__device__ __forceinline__ void sp2h(float a, float b, __half2& h, __half2& l) {
 __half ha = __float2half_rn(a), hb = __float2half_rn(b);
 h = __halves2half2(ha, hb);
 l = __halves2half2(__float2half_rn(a - __half2float(ha)),
                    __float2half_rn(b - __half2float(hb)));
}

__global__ void splitk(const float* __restrict__ in, int w) {
 __nv_bfloat16* oh = w==0 ? gXQ[0] : w==1 ? gXK[0] : w==2 ? gWQ[0] : gWK[0];
 __nv_bfloat16* ol = w==0 ? gXQ[1] : w==1 ? gXK[1] : w==2 ? gWQ[1] : gWK[1];
 int i = (blockIdx.x*256 + threadIdx.x)*2;
 float2 v = *(const float2*)&in[i];
 bf2 h, l; sp2(v.x, v.y, h, l);
 *(bf2*)&oh[i] = h; *(bf2*)&ol[i] = l;
}

__device__ __forceinline__ void lds(u32* r, u32 a) {
 asm volatile("ldmatrix.sync.aligned.m8n8.x4.shared.b16 {%0,%1,%2,%3},[%4];"
  : "=r"(r[0]), "=r"(r[1]), "=r"(r[2]), "=r"(r[3]) : "r"(a));
}
__device__ __forceinline__ void ldt(u32* r, u32 a) {
 asm volatile("ldmatrix.sync.aligned.m8n8.x4.trans.shared.b16 {%0,%1,%2,%3},[%4];"
  : "=r"(r[0]), "=r"(r[1]), "=r"(r[2]), "=r"(r[3]) : "r"(a));
}
__device__ __forceinline__ void mma(float* c, const u32* a, u32 b0, u32 b1) {
 asm volatile("mma.sync.aligned.m16n8k16.row.col.f32.bf16.bf16.f32 "
  "{%0,%1,%2,%3},{%4,%5,%6,%7},{%8,%9},{%0,%1,%2,%3};"
  : "+f"(c[0]), "+f"(c[1]), "+f"(c[2]), "+f"(c[3])
  : "r"(a[0]), "r"(a[1]), "r"(a[2]), "r"(a[3]), "r"(b0), "r"(b1));
}
__device__ __forceinline__ void mmah(float* c, const u32* a, u32 b0, u32 b1) {
 asm volatile("mma.sync.aligned.m16n8k16.row.col.f32.f16.f16.f32 "
  "{%0,%1,%2,%3},{%4,%5,%6,%7},{%8,%9},{%0,%1,%2,%3};"
  : "+f"(c[0]), "+f"(c[1]), "+f"(c[2]), "+f"(c[3])
  : "r"(a[0]), "r"(a[1]), "r"(a[2]), "r"(a[3]), "r"(b0), "r"(b1));
}
__device__ __forceinline__ void mma3(float* cA, float* cB, u32 (*A)[4], u32 (*B)[4]) {
 mma(cA, A[0], B[0][0], B[0][1]); mma(cB, A[0], B[0][2], B[0][3]);
 mma(cA, A[0], B[1][0], B[1][1]); mma(cB, A[0], B[1][2], B[1][3]);
 mma(cA, A[1], B[0][0], B[0][1]); mma(cB, A[1], B[0][2], B[0][3]);
}

__global__ __launch_bounds__(256, 2)
void pmma(const float* __restrict__ bq, const float* __restrict__ bk) {
 extern __shared__ char ps[];
 const u32 sb = (u32)__cvta_generic_to_shared(ps);
 const int tid = threadIdx.x, lane = tid & 31, wid = tid >> 5;
 const int mb = wid & 3, nb = wid >> 2, t = lane & 3;
 const int dst = blockIdx.x >= 256;
 const int row0 = (blockIdx.x & 255)*64;
 const __nv_bfloat16* Xp[2] = { dst ? gXK[0] : gXQ[0], dst ? gXK[1] : gXQ[1] };
 const __nv_bfloat16* Wp[2] = { dst ? gWK[0] : gWQ[0], dst ? gWK[1] : gWQ[1] };
 const float* bias = dst ? bk : bq;
 const int lr = lane & 7, qd = lane >> 3;
 const u32 aoff = ((mb*16 + (lane&15))*WST + (lane>>4)*8)*2;
 const u32 boff = ((nb*128 + (qd>>1)*8 + lr)*WST + (qd&1)*8)*2;
 float O[16][4];
#pragma unroll
 for (int j = 0; j < 16; j++) O[j][0] = O[j][1] = O[j][2] = O[j][3] = 0.f;
 for (int kc = 0; kc < 8; kc++) {
#pragma unroll
  for (int u = tid; u < 512; u += 256) {
   int r = u >> 3, c8 = u & 7;
   size_t gi = (size_t)(row0 + r)*DIN + kc*64 + c8*8;
   u32 so = (r*WST + c8*8)*2;
   *(uint4*)(ps + so) = *(const uint4*)(Xp[0] + gi);
   *(uint4*)(ps + 9216 + so) = *(const uint4*)(Xp[1] + gi);
  }
#pragma unroll
  for (int u = tid; u < 2048; u += 256) {
   int r = u >> 3, c8 = u & 7;
   size_t gi = (size_t)r*DIN + kc*64 + c8*8;
   u32 so = (r*WST + c8*8)*2;
   *(uint4*)(ps + 18432 + so) = *(const uint4*)(Wp[0] + gi);
   *(uint4*)(ps + 55296 + so) = *(const uint4*)(Wp[1] + gi);
  }
  __syncthreads();
#pragma unroll
  for (int kk = 0; kk < 4; kk++) {
   u32 A[2][4];
   lds(A[0], sb + aoff + kk*32);
   lds(A[1], sb + 9216 + aoff + kk*32);
#pragma unroll
   for (int pr = 0; pr < 8; pr++) {
    u32 B[2][4];
    u32 of = boff + pr*(16*WST*2) + kk*32;
    lds(B[0], sb + 18432 + of);
    lds(B[1], sb + 55296 + of);
    mma3(O[2*pr], O[2*pr+1], A, B);
   }
  }
  __syncthreads();
 }
 const int r0 = mb*16 + (lane >> 2), r1 = r0 + 8;
#pragma unroll
 for (int j = 0; j < 16; j++) {
  int n0 = nb*128 + j*8 + 2*t;
  float2 bv = *(const float2*)&bias[n0];
  float a0 = O[j][0] + bv.x, a1 = O[j][1] + bv.y;
  float b0 = O[j][2] + bv.x, b1 = O[j][3] + bv.y;
  size_t oa = (size_t)(row0+r0)*DD + n0, ob = (size_t)(row0+r1)*DD + n0;
  if (dst == 0) {
   *(__half2*)&gQ[oa] = __floats2half2_rn(a0, a1);
   *(__half2*)&gQ[ob] = __floats2half2_rn(b0, b1);
  } else {
   __half2 h, l;
   sp2h(a0, a1, h, l);
   *(__half2*)&gK[0][oa] = h; *(__half2*)&gK[1][oa] = l;
   sp2h(b0, b1, h, l);
   *(__half2*)&gK[0][ob] = h; *(__half2*)&gK[1][ob] = l;
  }
 }
}

__global__ __launch_bounds__(512, 1)
void attn(const float* __restrict__ val, const float* __restrict__ sfp,
          float* __restrict__ out) {
 extern __shared__ char sm[];
 const u32 sb = (u32)__cvta_generic_to_shared(sm);
 float* sMx = (float*)(sm + SMR);
 float* sM = sMx + 256;
 float* sL = sMx + 384;
 const int tid = threadIdx.x, lane = tid & 31, wid = tid >> 5;
 const int mb = wid & 3, nb = wid >> 2, t = lane & 3;
 const int b = blockIdx.x >> 6, q0 = (blockIdx.x & 63)*64;
 const float sf = *sfp;

 for (int u = tid; u < 2048; u += 512) {
  int r = u >> 5, c = u & 31;
  *(uint4*)(sm + (r*KST + c*8)*2) =
   ((const uint4*)(gQ + (size_t)(b*SS + q0 + r)*DD))[c];
 }
 if (tid < 128) sM[tid] = -1e30f;
 if (tid < 256) sL[tid] = 0.f;

 const int lr = lane & 7, qd = lane >> 3;
 const u32 aoff = ((mb*16 + (lane&15))*KST + (lane>>4)*8)*2;
 const u32 koff = ((nb*16 + (qd>>1)*8 + lr)*KST + (qd&1)*8)*2;
 const u32 voff = (((qd&1)*8 + lr)*KST + nb*64 + (qd>>1)*8)*2;
 const u32 poff = ((mb*16 + (lane&15))*PST + (lane>>4)*8)*2;

 float O[8][4];
#pragma unroll
 for (int j = 0; j < 8; j++) O[j][0] = O[j][1] = O[j][2] = O[j][3] = 0.f;
 int rr[2]; rr[0] = mb*16 + (lane >> 2); rr[1] = rr[0] + 8;

 for (int kt = 0; kt < SS/64; kt++) {
  for (int u = tid; u < 2048; u += 512) {
   int r = u >> 5, c = u & 31;
   size_t gi = (size_t)(b*SS + kt*64 + r)*DD;
   u32 so = (r*KST + c*8)*2;
   *(uint4*)(sm + TSZ + so) = ((const uint4*)(gK[0] + gi))[c];
   *(uint4*)(sm + 2*TSZ + so) = ((const uint4*)(gK[1] + gi))[c];
  }
  for (int u = tid; u < 4096; u += 512) {
   int r = u >> 6, c = u & 63;
   float4 v = ((const float4*)&val[(size_t)(b*SS + kt*64 + r)*DD])[c];
   u32 so = (r*KST + c*4)*2;
   *(__half2*)(sm + 3*TSZ + so) = __floats2half2_rn(v.x, v.y);
   *(__half2*)(sm + 3*TSZ + so + 4) = __floats2half2_rn(v.z, v.w);
  }
  __syncthreads();

  float Sv[2][4];
#pragma unroll
  for (int j = 0; j < 2; j++) Sv[j][0] = Sv[j][1] = Sv[j][2] = Sv[j][3] = 0.f;
#pragma unroll 4
  for (int kk = 0; kk < 16; kk++) {
   u32 A[4], B0[4], B1[4];
   lds(A, sb + aoff + kk*32);
   u32 of = koff + kk*32;
   lds(B0, sb + TSZ + of);
   lds(B1, sb + 2*TSZ + of);
   mmah(Sv[0], A, B0[0], B0[1]); mmah(Sv[1], A, B0[2], B0[3]);
   mmah(Sv[0], A, B1[0], B1[1]); mmah(Sv[1], A, B1[2], B1[3]);
  }

  float mx[2] = {-1e30f, -1e30f};
#pragma unroll
  for (int j = 0; j < 2; j++) {
   Sv[j][0] *= sf; Sv[j][1] *= sf; Sv[j][2] *= sf; Sv[j][3] *= sf;
   mx[0] = fmaxf(mx[0], fmaxf(Sv[j][0], Sv[j][1]));
   mx[1] = fmaxf(mx[1], fmaxf(Sv[j][2], Sv[j][3]));
  }
#pragma unroll
  for (int h = 0; h < 2; h++) {
   mx[h] = fmaxf(mx[h], __shfl_xor_sync(~0u, mx[h], 1));
   mx[h] = fmaxf(mx[h], __shfl_xor_sync(~0u, mx[h], 2));
   if (t == 0) sMx[nb*64 + rr[h]] = mx[h];
  }
  __syncthreads();

  const int par = kt & 1;
  float mn[2], sc[2], rs[2];
#pragma unroll
  for (int h = 0; h < 2; h++) {
   float mp = sM[par*64 + rr[h]];
   mn[h] = fmaxf(fmaxf(mp, fmaxf(sMx[rr[h]], sMx[64 + rr[h]])),
                 fmaxf(sMx[128 + rr[h]], sMx[192 + rr[h]]));
   sc[h] = __expf(mp - mn[h]);
   rs[h] = 0.f;
  }
#pragma unroll
  for (int j = 0; j < 2; j++) {
#pragma unroll
   for (int h = 0; h < 2; h++) {
    float pa = __expf(Sv[j][2*h] - mn[h]);
    float pb = __expf(Sv[j][2*h+1] - mn[h]);
    rs[h] += pa + pb;
    u32 po = (rr[h]*PST + nb*16 + j*8 + 2*t)*2;
    *(__half2*)(sm + SMP + po) = __floats2half2_rn(pa, pb);
   }
  }
#pragma unroll
  for (int h = 0; h < 2; h++) {
   rs[h] += __shfl_xor_sync(~0u, rs[h], 1);
   rs[h] += __shfl_xor_sync(~0u, rs[h], 2);
   if (t == 0) {
    sL[nb*64 + rr[h]] = sL[nb*64 + rr[h]]*sc[h] + rs[h];
    if (nb == 0) sM[(par^1)*64 + rr[h]] = mn[h];
   }
  }
#pragma unroll
  for (int j = 0; j < 8; j++) {
   O[j][0] *= sc[0]; O[j][1] *= sc[0]; O[j][2] *= sc[1]; O[j][3] *= sc[1];
  }
  __syncthreads();
#pragma unroll
  for (int ks = 0; ks < 4; ks++) {
   u32 P1[4];
   lds(P1, sb + SMP + poff + ks*32);
#pragma unroll
   for (int pr = 0; pr < 4; pr++) {
    u32 Vf[4];
    ldt(Vf, sb + 3*TSZ + voff + ks*(16*KST*2) + pr*32);
    mmah(O[2*pr], P1, Vf[0], Vf[1]);
    mmah(O[2*pr+1], P1, Vf[2], Vf[3]);
   }
  }
  __syncthreads();
 }

 float i0 = 1.f/(sL[rr[0]] + sL[64+rr[0]] + sL[128+rr[0]] + sL[192+rr[0]]);
 float i1 = 1.f/(sL[rr[1]] + sL[64+rr[1]] + sL[128+rr[1]] + sL[192+rr[1]]);
#pragma unroll
 for (int j = 0; j < 8; j++) {
  size_t oa = (size_t)(b*SS + q0 + rr[0])*DD + nb*64 + j*8 + 2*t;
  size_t ob = (size_t)(b*SS + q0 + rr[1])*DD + nb*64 + j*8 + 2*t;
  *(float2*)&out[oa] = make_float2(O[j][0]*i0, O[j][1]*i0);
  *(float2*)&out[ob] = make_float2(O[j][2]*i1, O[j][3]*i1);
 }
}

extern "C" void kernel_launch(void* const* d_in, const int* in_sizes, int n_in,
                              void* d_out, int out_size) {
 cudaFuncSetAttribute(attn, cudaFuncAttributeMaxDynamicSharedMemorySize, SMT);
 cudaFuncSetAttribute(pmma, cudaFuncAttributeMaxDynamicSharedMemorySize, 92160);
 splitk<<<(BB*SS*DIN)/512, 256>>>((const float*)d_in[0], 0);
 splitk<<<(BB*SS*DIN)/512, 256>>>((const float*)d_in[1], 1);
 splitk<<<(DD*DIN)/512, 256>>>((const float*)d_in[3], 2);
 splitk<<<(DD*DIN)/512, 256>>>((const float*)d_in[5], 3);
 pmma<<<512, 256, 92160>>>((const float*)d_in[4], (const float*)d_in[6]);
 attn<<<BB*(SS/64), 512, SMT>>>((const float*)d_in[2], (const float*)d_in[7],
                                (float*)d_out);
}

// round 15
// speedup vs baseline: 4.2053x; 1.3344x over previous
#include <cuda_runtime.h>
#include <cuda_bf16.h>
#include <cuda_fp16.h>
#include <cstdint>
#define BB 4
#define SS 4096
#define DIN 512
#define DD 256
#define KST 264
#define PST 72
#define WST 72
#define TSZ 33792
#define SMP 168960
#define SMR 178176
#define SMT 180736
typedef __nv_bfloat162 bf2;
typedef uint32_t u32;

__device__ __half gQ[BB*SS*DD];
__device__ __half gK[2][BB*SS*DD];
__device__ __half gV[BB*SS*DD];
__device__ __nv_bfloat16 gXQ[2][BB*SS*DIN], gXK[2][BB*SS*DIN];
__device__ __nv_bfloat16 gWQ[2][DD*DIN], gWK[2][DD*DIN];

__device__ __forceinline__ void sp2(float a, float b, bf2& h, bf2& l) {
 h.x = __float2bfloat16(a); h.y = __float2bfloat16(b);
 l.x = __float2bfloat16(a - __bfloat162float(h.x));
 l.y = __float2bfloat16(b - __bfloat162float(h.y));
}
__device__ __forceinline__ void sp2h(float a, float b, __half2& h, __half2& l) {
 __half ha = __float2half_rn(a), hb = __float2half_rn(b);
 h = __halves2half2(ha, hb);
 l = __halves2half2(__float2half_rn(a - __half2float(ha)),
                    __float2half_rn(b - __half2float(hb)));
}

__global__ void splitk(const float* __restrict__ in, int w) {
 __nv_bfloat16* oh = w==0 ? gXQ[0] : w==1 ? gXK[0] : w==2 ? gWQ[0] : gWK[0];
 __nv_bfloat16* ol = w==0 ? gXQ[1] : w==1 ? gXK[1] : w==2 ? gWQ[1] : gWK[1];
 int i = (blockIdx.x*256 + threadIdx.x)*2;
 float2 v = *(const float2*)&in[i];
 bf2 h, l; sp2(v.x, v.y, h, l);
 *(bf2*)&oh[i] = h; *(bf2*)&ol[i] = l;
}

__global__ void vconv(const float* __restrict__ in) {
 int i = (blockIdx.x*256 + threadIdx.x)*4;
 float4 v = *(const float4*)&in[i];
 __half2 a = __floats2half2_rn(v.x, v.y), b = __floats2half2_rn(v.z, v.w);
 *(__half2*)&gV[i] = a; *(__half2*)&gV[i+2] = b;
}

__device__ __forceinline__ void cpa(u32 dst, const void* src) {
 asm volatile("cp.async.ca.shared.global [%0], [%1], 16;" :: "r"(dst), "l"(src));
}
#define CPCOMMIT() asm volatile("cp.async.commit_group;" ::: "memory")
#define CPWAIT0() asm volatile("cp.async.wait_group 0;" ::: "memory")

__device__ __forceinline__ void lds(u32* r, u32 a) {
 asm volatile("ldmatrix.sync.aligned.m8n8.x4.shared.b16 {%0,%1,%2,%3},[%4];"
  : "=r"(r[0]), "=r"(r[1]), "=r"(r[2]), "=r"(r[3]) : "r"(a));
}
__device__ __forceinline__ void ldt(u32* r, u32 a) {
 asm volatile("ldmatrix.sync.aligned.m8n8.x4.trans.shared.b16 {%0,%1,%2,%3},[%4];"
  : "=r"(r[0]), "=r"(r[1]), "=r"(r[2]), "=r"(r[3]) : "r"(a));
}
__device__ __forceinline__ void mma(float* c, const u32* a, u32 b0, u32 b1) {
 asm volatile("mma.sync.aligned.m16n8k16.row.col.f32.bf16.bf16.f32 "
  "{%0,%1,%2,%3},{%4,%5,%6,%7},{%8,%9},{%0,%1,%2,%3};"
  : "+f"(c[0]), "+f"(c[1]), "+f"(c[2]), "+f"(c[3])
  : "r"(a[0]), "r"(a[1]), "r"(a[2]), "r"(a[3]), "r"(b0), "r"(b1));
}
__device__ __forceinline__ void mmah(float* c, const u32* a, u32 b0, u32 b1) {
 asm volatile("mma.sync.aligned.m16n8k16.row.col.f32.f16.f16.f32 "
  "{%0,%1,%2,%3},{%4,%5,%6,%7},{%8,%9},{%0,%1,%2,%3};"
  : "+f"(c[0]), "+f"(c[1]), "+f"(c[2]), "+f"(c[3])
  : "r"(a[0]), "r"(a[1]), "r"(a[2]), "r"(a[3]), "r"(b0), "r"(b1));
}
__device__ __forceinline__ void mma3(float* cA, float* cB, u32 (*A)[4], u32 (*B)[4]) {
 mma(cA, A[0], B[0][0], B[0][1]); mma(cB, A[0], B[0][2], B[0][3]);
 mma(cA, A[0], B[1][0], B[1][1]); mma(cB, A[0], B[1][2], B[1][3]);
 mma(cA, A[1], B[0][0], B[0][1]); mma(cB, A[1], B[0][2], B[0][3]);
}

__global__ __launch_bounds__(256, 2)
void pmma(const float* __restrict__ bq, const float* __restrict__ bk) {
 extern __shared__ char ps[];
 const u32 sb = (u32)__cvta_generic_to_shared(ps);
 const int tid = threadIdx.x, lane = tid & 31, wid = tid >> 5;
 const int mb = wid & 3, nb = wid >> 2, t = lane & 3;
 const int dst = blockIdx.x >= 256;
 const int row0 = (blockIdx.x & 255)*64;
 const __nv_bfloat16* Xp[2] = { dst ? gXK[0] : gXQ[0], dst ? gXK[1] : gXQ[1] };
 const __nv_bfloat16* Wp[2] = { dst ? gWK[0] : gWQ[0], dst ? gWK[1] : gWQ[1] };
 const float* bias = dst ? bk : bq;
 const int lr = lane & 7, qd = lane >> 3;
 const u32 aoff = ((mb*16 + (lane&15))*WST + (lane>>4)*8)*2;
 const u32 boff = ((nb*128 + (qd>>1)*8 + lr)*WST + (qd&1)*8)*2;
 float O[16][4];
#pragma unroll
 for (int j = 0; j < 16; j++) O[j][0] = O[j][1] = O[j][2] = O[j][3] = 0.f;
 for (int kc = 0; kc < 8; kc++) {
#pragma unroll
  for (int u = tid; u < 512; u += 256) {
   int r = u >> 3, c8 = u & 7;
   size_t gi = (size_t)(row0 + r)*DIN + kc*64 + c8*8;
   u32 so = (r*WST + c8*8)*2;
   *(uint4*)(ps + so) = *(const uint4*)(Xp[0] + gi);
   *(uint4*)(ps + 9216 + so) = *(const uint4*)(Xp[1] + gi);
  }
#pragma unroll
  for (int u = tid; u < 2048; u += 256) {
   int r = u >> 3, c8 = u & 7;
   size_t gi = (size_t)r*DIN + kc*64 + c8*8;
   u32 so = (r*WST + c8*8)*2;
   *(uint4*)(ps + 18432 + so) = *(const uint4*)(Wp[0] + gi);
   *(uint4*)(ps + 55296 + so) = *(const uint4*)(Wp[1] + gi);
  }
  __syncthreads();
#pragma unroll
  for (int kk = 0; kk < 4; kk++) {
   u32 A[2][4];
   lds(A[0], sb + aoff + kk*32);
   lds(A[1], sb + 9216 + aoff + kk*32);
#pragma unroll
   for (int pr = 0; pr < 8; pr++) {
    u32 B[2][4];
    u32 of = boff + pr*(16*WST*2) + kk*32;
    lds(B[0], sb + 18432 + of);
    lds(B[1], sb + 55296 + of);
    mma3(O[2*pr], O[2*pr+1], A, B);
   }
  }
  __syncthreads();
 }
 const int r0 = mb*16 + (lane >> 2), r1 = r0 + 8;
#pragma unroll
 for (int j = 0; j < 16; j++) {
  int n0 = nb*128 + j*8 + 2*t;
  float2 bv = *(const float2*)&bias[n0];
  float a0 = O[j][0] + bv.x, a1 = O[j][1] + bv.y;
  float b0 = O[j][2] + bv.x, b1 = O[j][3] + bv.y;
  size_t oa = (size_t)(row0+r0)*DD + n0, ob = (size_t)(row0+r1)*DD + n0;
  if (dst == 0) {
   *(__half2*)&gQ[oa] = __floats2half2_rn(a0, a1);
   *(__half2*)&gQ[ob] = __floats2half2_rn(b0, b1);
  } else {
   __half2 h, l;
   sp2h(a0, a1, h, l);
   *(__half2*)&gK[0][oa] = h; *(__half2*)&gK[1][oa] = l;
   sp2h(b0, b1, h, l);
   *(__half2*)&gK[0][ob] = h; *(__half2*)&gK[1][ob] = l;
  }
 }
}

// smem: Q 0 | Khi 1*TSZ | Klo 2*TSZ | V0 3*TSZ | V1 4*TSZ | P 5*TSZ | red
__device__ __forceinline__ void stage_kv(u32 sb, int tid, int b, int kt, int vb) {
 for (int u = tid; u < 2048; u += 512) {
  int r = u >> 5, c = u & 31;
  size_t gi = (size_t)(b*SS + kt*64 + r)*DD + c*8;
  u32 so = (r*KST + c*8)*2;
  cpa(sb + TSZ + so, gK[0] + gi);
  cpa(sb + 2*TSZ + so, gK[1] + gi);
  cpa(sb + (3+vb)*TSZ + so, gV + gi);
 }
 CPCOMMIT();
}

__global__ __launch_bounds__(512, 1)
void attn(const float* __restrict__ sfp, float* __restrict__ out) {
 extern __shared__ char sm[];
 const u32 sb = (u32)__cvta_generic_to_shared(sm);
 float* sMx = (float*)(sm + SMR);
 float* sM = sMx + 256;
 float* sL = sMx + 384;
 const int tid = threadIdx.x, lane = tid & 31, wid = tid >> 5;
 const int mb = wid & 3, nb = wid >> 2, t = lane & 3;
 const int b = blockIdx.x >> 6, q0 = (blockIdx.x & 63)*64;
 const float sf = *sfp;

 stage_kv(sb, tid, b, 0, 0);
 for (int u = tid; u < 2048; u += 512) {
  int r = u >> 5, c = u & 31;
  *(uint4*)(sm + (r*KST + c*8)*2) =
   ((const uint4*)(gQ + (size_t)(b*SS + q0 + r)*DD))[c];
 }
 if (tid < 128) sM[tid] = -1e30f;
 if (tid < 256) sL[tid] = 0.f;

 const int lr = lane & 7, qd = lane >> 3;
 const u32 aoff = ((mb*16 + (lane&15))*KST + (lane>>4)*8)*2;
 const u32 koff = ((nb*16 + (qd>>1)*8 + lr)*KST + (qd&1)*8)*2;
 const u32 voff = (((qd&1)*8 + lr)*KST + nb*64 + (qd>>1)*8)*2;
 const u32 poff = ((mb*16 + (lane&15))*PST + (lane>>4)*8)*2;

 float O[8][4];
#pragma unroll
 for (int j = 0; j < 8; j++) O[j][0] = O[j][1] = O[j][2] = O[j][3] = 0.f;
 int rr[2]; rr[0] = mb*16 + (lane >> 2); rr[1] = rr[0] + 8;

 CPWAIT0();
 __syncthreads();

 for (int kt = 0; kt < SS/64; kt++) {
  const int vb = kt & 1;
  float Sv[2][4];
#pragma unroll
  for (int j = 0; j < 2; j++) Sv[j][0] = Sv[j][1] = Sv[j][2] = Sv[j][3] = 0.f;
#pragma unroll 4
  for (int kk = 0; kk < 16; kk++) {
   u32 A[4], B0[4], B1[4];
   lds(A, sb + aoff + kk*32);
   u32 of = koff + kk*32;
   lds(B0, sb + TSZ + of);
   lds(B1, sb + 2*TSZ + of);
   mmah(Sv[0], A, B0[0], B0[1]); mmah(Sv[1], A, B0[2], B0[3]);
   mmah(Sv[0], A, B1[0], B1[1]); mmah(Sv[1], A, B1[2], B1[3]);
  }

  float mx[2] = {-1e30f, -1e30f};
#pragma unroll
  for (int j = 0; j < 2; j++) {
   Sv[j][0] *= sf; Sv[j][1] *= sf; Sv[j][2] *= sf; Sv[j][3] *= sf;
   mx[0] = fmaxf(mx[0], fmaxf(Sv[j][0], Sv[j][1]));
   mx[1] = fmaxf(mx[1], fmaxf(Sv[j][2], Sv[j][3]));
  }
#pragma unroll
  for (int h = 0; h < 2; h++) {
   mx[h] = fmaxf(mx[h], __shfl_xor_sync(~0u, mx[h], 1));
   mx[h] = fmaxf(mx[h], __shfl_xor_sync(~0u, mx[h], 2));
   if (t == 0) sMx[nb*64 + rr[h]] = mx[h];
  }
  __syncthreads();
  // K buffers + V[1-vb] now free: prefetch next tile while softmax+PV run
  if (kt < SS/64 - 1) stage_kv(sb, tid, b, kt + 1, 1 - vb);

  const int par = kt & 1;
  float mn[2], sc[2], rs[2];
#pragma unroll
  for (int h = 0; h < 2; h++) {
   float mp = sM[par*64 + rr[h]];
   mn[h] = fmaxf(fmaxf(mp, fmaxf(sMx[rr[h]], sMx[64 + rr[h]])),
                 fmaxf(sMx[128 + rr[h]], sMx[192 + rr[h]]));
   sc[h] = __expf(mp - mn[h]);
   rs[h] = 0.f;
  }
#pragma unroll
  for (int j = 0; j < 2; j++) {
#pragma unroll
   for (int h = 0; h < 2; h++) {
    float pa = __expf(Sv[j][2*h] - mn[h]);
    float pb = __expf(Sv[j][2*h+1] - mn[h]);
    rs[h] += pa + pb;
    u32 po = (rr[h]*PST + nb*16 + j*8 + 2*t)*2;
    *(__half2*)(sm + SMP + po) = __floats2half2_rn(pa, pb);
   }
  }
#pragma unroll
  for (int h = 0; h < 2; h++) {
   rs[h] += __shfl_xor_sync(~0u, rs[h], 1);
   rs[h] += __shfl_xor_sync(~0u, rs[h], 2);
   if (t == 0) {
    sL[nb*64 + rr[h]] = sL[nb*64 + rr[h]]*sc[h] + rs[h];
    if (nb == 0) sM[(par^1)*64 + rr[h]] = mn[h];
   }
  }
#pragma unroll
  for (int j = 0; j < 8; j++) {
   O[j][0] *= sc[0]; O[j][1] *= sc[0]; O[j][2] *= sc[1]; O[j][3] *= sc[1];
  }
  __syncthreads();
#pragma unroll
  for (int ks = 0; ks < 4; ks++) {
   u32 P1[4];
   lds(P1, sb + SMP + poff + ks*32);
#pragma unroll
   for (int pr = 0; pr < 4; pr++) {
    u32 Vf[4];
    ldt(Vf, sb + (3+vb)*TSZ + voff + ks*(16*KST*2) + pr*32);
    mmah(O[2*pr], P1, Vf[0], Vf[1]);
    mmah(O[2*pr+1], P1, Vf[2], Vf[3]);
   }
  }
  CPWAIT0();
  __syncthreads();
 }

 float i0 = 1.f/(sL[rr[0]] + sL[64+rr[0]] + sL[128+rr[0]] + sL[192+rr[0]]);
 float i1 = 1.f/(sL[rr[1]] + sL[64+rr[1]] + sL[128+rr[1]] + sL[192+rr[1]]);
#pragma unroll
 for (int j = 0; j < 8; j++) {
  size_t oa = (size_t)(b*SS + q0 + rr[0])*DD + nb*64 + j*8 + 2*t;
  size_t ob = (size_t)(b*SS + q0 + rr[1])*DD + nb*64 + j*8 + 2*t;
  *(float2*)&out[oa] = make_float2(O[j][0]*i0, O[j][1]*i0);
  *(float2*)&out[ob] = make_float2(O[j][2]*i1, O[j][3]*i1);
 }
}

extern "C" void kernel_launch(void* const* d_in, const int* in_sizes, int n_in,
                              void* d_out, int out_size) {
 cudaFuncSetAttribute(attn, cudaFuncAttributeMaxDynamicSharedMemorySize, SMT);
 cudaFuncSetAttribute(pmma, cudaFuncAttributeMaxDynamicSharedMemorySize, 92160);
 splitk<<<(BB*SS*DIN)/512, 256>>>((const float*)d_in[0], 0);
 splitk<<<(BB*SS*DIN)/512, 256>>>((const float*)d_in[1], 1);
 splitk<<<(DD*DIN)/512, 256>>>((const float*)d_in[3], 2);
 splitk<<<(DD*DIN)/512, 256>>>((const float*)d_in[5], 3);
 vconv<<<(BB*SS*DD)/1024, 256>>>((const float*)d_in[2]);
 pmma<<<512, 256, 92160>>>((const float*)d_in[4], (const float*)d_in[6]);
 attn<<<BB*(SS/64), 512, SMT>>>((const float*)d_in[7], (float*)d_out);
}

// round 16
// speedup vs baseline: 5.1791x; 1.2316x over previous
#include <cuda_runtime.h>
#include <cuda_bf16.h>
#include <cuda_fp16.h>
#include <cstdint>
#define BB 4
#define SS 4096
#define DIN 512
#define DD 256
#define KST 264
#define PST 72
#define WST 72
#define TSZ 33792
#define SMP 202752
#define SMR 221184
#define SMT 224256
typedef __nv_bfloat162 bf2;
typedef uint32_t u32;

__device__ __half gQ[BB*SS*DD];
__device__ __half gK[2][BB*SS*DD];
__device__ __half gV[BB*SS*DD];
__device__ __nv_bfloat16 gXQ[2][BB*SS*DIN], gXK[2][BB*SS*DIN];
__device__ __nv_bfloat16 gWQ[2][DD*DIN], gWK[2][DD*DIN];

__device__ __forceinline__ void sp2(float a, float b, bf2& h, bf2& l) {
 h.x = __float2bfloat16(a); h.y = __float2bfloat16(b);
 l.x = __float2bfloat16(a - __bfloat162float(h.x));
 l.y = __float2bfloat16(b - __bfloat162float(h.y));
}
__device__ __forceinline__ void sp2h(float a, float b, __half2& h, __half2& l) {
 __half ha = __float2half_rn(a), hb = __float2half_rn(b);
 h = __halves2half2(ha, hb);
 l = __halves2half2(__float2half_rn(a - __half2float(ha)),
                    __float2half_rn(b - __half2float(hb)));
}

__global__ void splitk(const float* __restrict__ in, int w) {
 __nv_bfloat16* oh = w==0 ? gXQ[0] : w==1 ? gXK[0] : w==2 ? gWQ[0] : gWK[0];
 __nv_bfloat16* ol = w==0 ? gXQ[1] : w==1 ? gXK[1] : w==2 ? gWQ[1] : gWK[1];
 int i = (blockIdx.x*256 + threadIdx.x)*2;
 float2 v = *(const float2*)&in[i];
 bf2 h, l; sp2(v.x, v.y, h, l);
 *(bf2*)&oh[i] = h; *(bf2*)&ol[i] = l;
}

__global__ void vconv(const float* __restrict__ in) {
 int i = (blockIdx.x*256 + threadIdx.x)*4;
 float4 v = *(const float4*)&in[i];
 *(__half2*)&gV[i] = __floats2half2_rn(v.x, v.y);
 *(__half2*)&gV[i+2] = __floats2half2_rn(v.z, v.w);
}

__device__ __forceinline__ void cpa(u32 dst, const void* src) {
 asm volatile("cp.async.ca.shared.global [%0], [%1], 16;" :: "r"(dst), "l"(src));
}
#define CPCOMMIT() asm volatile("cp.async.commit_group;" ::: "memory")
#define CPWAIT0() asm volatile("cp.async.wait_group 0;" ::: "memory")

__device__ __forceinline__ void lds(u32* r, u32 a) {
 asm volatile("ldmatrix.sync.aligned.m8n8.x4.shared.b16 {%0,%1,%2,%3},[%4];"
  : "=r"(r[0]), "=r"(r[1]), "=r"(r[2]), "=r"(r[3]) : "r"(a));
}
__device__ __forceinline__ void ldt(u32* r, u32 a) {
 asm volatile("ldmatrix.sync.aligned.m8n8.x4.trans.shared.b16 {%0,%1,%2,%3},[%4];"
  : "=r"(r[0]), "=r"(r[1]), "=r"(r[2]), "=r"(r[3]) : "r"(a));
}
__device__ __forceinline__ void mma(float* c, const u32* a, u32 b0, u32 b1) {
 asm volatile("mma.sync.aligned.m16n8k16.row.col.f32.bf16.bf16.f32 "
  "{%0,%1,%2,%3},{%4,%5,%6,%7},{%8,%9},{%0,%1,%2,%3};"
  : "+f"(c[0]), "+f"(c[1]), "+f"(c[2]), "+f"(c[3])
  : "r"(a[0]), "r"(a[1]), "r"(a[2]), "r"(a[3]), "r"(b0), "r"(b1));
}
__device__ __forceinline__ void mmah(float* c, const u32* a, u32 b0, u32 b1) {
 asm volatile("mma.sync.aligned.m16n8k16.row.col.f32.f16.f16.f32 "
  "{%0,%1,%2,%3},{%4,%5,%6,%7},{%8,%9},{%0,%1,%2,%3};"
  : "+f"(c[0]), "+f"(c[1]), "+f"(c[2]), "+f"(c[3])
  : "r"(a[0]), "r"(a[1]), "r"(a[2]), "r"(a[3]), "r"(b0), "r"(b1));
}
__device__ __forceinline__ void mma3(float* cA, float* cB, u32 (*A)[4], u32 (*B)[4]) {
 mma(cA, A[0], B[0][0], B[0][1]); mma(cB, A[0], B[0][2], B[0][3]);
 mma(cA, A[0], B[1][0], B[1][1]); mma(cB, A[0], B[1][2], B[1][3]);
 mma(cA, A[1], B[0][0], B[0][1]); mma(cB, A[1], B[0][2], B[0][3]);
}

__global__ __launch_bounds__(256, 2)
void pmma(const float* __restrict__ bq, const float* __restrict__ bk) {
 extern __shared__ char ps[];
 const u32 sb = (u32)__cvta_generic_to_shared(ps);
 const int tid = threadIdx.x, lane = tid & 31, wid = tid >> 5;
 const int mb = wid & 3, nb = wid >> 2, t = lane & 3;
 const int dst = blockIdx.x >= 256;
 const int row0 = (blockIdx.x & 255)*64;
 const __nv_bfloat16* Xp[2] = { dst ? gXK[0] : gXQ[0], dst ? gXK[1] : gXQ[1] };
 const __nv_bfloat16* Wp[2] = { dst ? gWK[0] : gWQ[0], dst ? gWK[1] : gWQ[1] };
 const float* bias = dst ? bk : bq;
 const int lr = lane & 7, qd = lane >> 3;
 const u32 aoff = ((mb*16 + (lane&15))*WST + (lane>>4)*8)*2;
 const u32 boff = ((nb*128 + (qd>>1)*8 + lr)*WST + (qd&1)*8)*2;
 float O[16][4];
#pragma unroll
 for (int j = 0; j < 16; j++) O[j][0] = O[j][1] = O[j][2] = O[j][3] = 0.f;
 for (int kc = 0; kc < 8; kc++) {
#pragma unroll
  for (int u = tid; u < 512; u += 256) {
   int r = u >> 3, c8 = u & 7;
   size_t gi = (size_t)(row0 + r)*DIN + kc*64 + c8*8;
   u32 so = (r*WST + c8*8)*2;
   *(uint4*)(ps + so) = *(const uint4*)(Xp[0] + gi);
   *(uint4*)(ps + 9216 + so) = *(const uint4*)(Xp[1] + gi);
  }
#pragma unroll
  for (int u = tid; u < 2048; u += 256) {
   int r = u >> 3, c8 = u & 7;
   size_t gi = (size_t)r*DIN + kc*64 + c8*8;
   u32 so = (r*WST + c8*8)*2;
   *(uint4*)(ps + 18432 + so) = *(const uint4*)(Wp[0] + gi);
   *(uint4*)(ps + 55296 + so) = *(const uint4*)(Wp[1] + gi);
  }
  __syncthreads();
#pragma unroll
  for (int kk = 0; kk < 4; kk++) {
   u32 A[2][4];
   lds(A[0], sb + aoff + kk*32);
   lds(A[1], sb + 9216 + aoff + kk*32);
#pragma unroll
   for (int pr = 0; pr < 8; pr++) {
    u32 B[2][4];
    u32 of = boff + pr*(16*WST*2) + kk*32;
    lds(B[0], sb + 18432 + of);
    lds(B[1], sb + 55296 + of);
    mma3(O[2*pr], O[2*pr+1], A, B);
   }
  }
  __syncthreads();
 }
 const int r0 = mb*16 + (lane >> 2), r1 = r0 + 8;
#pragma unroll
 for (int j = 0; j < 16; j++) {
  int n0 = nb*128 + j*8 + 2*t;
  float2 bv = *(const float2*)&bias[n0];
  float a0 = O[j][0] + bv.x, a1 = O[j][1] + bv.y;
  float b0 = O[j][2] + bv.x, b1 = O[j][3] + bv.y;
  size_t oa = (size_t)(row0+r0)*DD + n0, ob = (size_t)(row0+r1)*DD + n0;
  if (dst == 0) {
   *(__half2*)&gQ[oa] = __floats2half2_rn(a0, a1);
   *(__half2*)&gQ[ob] = __floats2half2_rn(b0, b1);
  } else {
   __half2 h, l;
   sp2h(a0, a1, h, l);
   *(__half2*)&gK[0][oa] = h; *(__half2*)&gK[1][oa] = l;
   sp2h(b0, b1, h, l);
   *(__half2*)&gK[0][ob] = h; *(__half2*)&gK[1][ob] = l;
  }
 }
}

// smem: Q 0..2*TSZ | Khi 2*TSZ | Klo 3*TSZ | V0 4*TSZ | V1 5*TSZ | P SMP | red SMR
__device__ __forceinline__ void stage_kv(u32 sb, int tid, int b, int kt, int vb) {
 for (int u = tid; u < 2048; u += 512) {
  int r = u >> 5, c = u & 31;
  size_t gi = (size_t)(b*SS + kt*64 + r)*DD + c*8;
  u32 so = (r*KST + c*8)*2;
  cpa(sb + 2*TSZ + so, gK[0] + gi);
  cpa(sb + 3*TSZ + so, gK[1] + gi);
  cpa(sb + (4+vb)*TSZ + so, gV + gi);
 }
 CPCOMMIT();
}

__global__ __launch_bounds__(512, 1)
void attn(const float* __restrict__ sfp, float* __restrict__ out) {
 extern __shared__ char sm[];
 const u32 sb = (u32)__cvta_generic_to_shared(sm);
 float* sMx = (float*)(sm + SMR);   // [2][128]
 float* sM = sMx + 256;             // [2][128]
 float* sL = sMx + 512;             // [2][128]
 const int tid = threadIdx.x, lane = tid & 31, wid = tid >> 5;
 const int mb = wid & 7, nb = wid >> 3, t = lane & 3;
 const int b = blockIdx.x >> 5, q0 = (blockIdx.x & 31)*128;
 const float sf = *sfp;

 stage_kv(sb, tid, b, 0, 0);
 for (int u = tid; u < 4096; u += 512) {
  int r = u >> 5, c = u & 31;
  *(uint4*)(sm + (r*KST + c*8)*2) =
   ((const uint4*)(gQ + (size_t)(b*SS + q0 + r)*DD))[c];
 }
 if (tid < 256) { sM[tid] = -1e30f; sL[tid] = 0.f; }

 const int lr = lane & 7, qd = lane >> 3;
 const u32 aoff = ((mb*16 + (lane&15))*KST + (lane>>4)*8)*2;
 const u32 koff = ((nb*32 + (qd>>1)*8 + lr)*KST + (qd&1)*8)*2;
 const u32 voff = (((qd&1)*8 + lr)*KST + nb*128 + (qd>>1)*8)*2;
 const u32 poff = ((mb*16 + (lane&15))*PST + (lane>>4)*8)*2;

 float O[16][4];
#pragma unroll
 for (int j = 0; j < 16; j++) O[j][0] = O[j][1] = O[j][2] = O[j][3] = 0.f;
 int rr[2]; rr[0] = mb*16 + (lane >> 2); rr[1] = rr[0] + 8;

 CPWAIT0();
 __syncthreads();

 for (int kt = 0; kt < SS/64; kt++) {
  const int vb = kt & 1;
  float Sv[4][4];
#pragma unroll
  for (int j = 0; j < 4; j++) Sv[j][0] = Sv[j][1] = Sv[j][2] = Sv[j][3] = 0.f;
#pragma unroll 4
  for (int kk = 0; kk < 16; kk++) {
   u32 A[4];
   lds(A, sb + aoff + kk*32);
#pragma unroll
   for (int n2 = 0; n2 < 2; n2++) {
    u32 B0[4], B1[4];
    u32 of = koff + n2*(16*KST*2) + kk*32;
    lds(B0, sb + 2*TSZ + of);
    lds(B1, sb + 3*TSZ + of);
    mmah(Sv[2*n2], A, B0[0], B0[1]); mmah(Sv[2*n2+1], A, B0[2], B0[3]);
    mmah(Sv[2*n2], A, B1[0], B1[1]); mmah(Sv[2*n2+1], A, B1[2], B1[3]);
   }
  }

  float mx[2] = {-1e30f, -1e30f};
#pragma unroll
  for (int j = 0; j < 4; j++) {
   Sv[j][0] *= sf; Sv[j][1] *= sf; Sv[j][2] *= sf; Sv[j][3] *= sf;
   mx[0] = fmaxf(mx[0], fmaxf(Sv[j][0], Sv[j][1]));
   mx[1] = fmaxf(mx[1], fmaxf(Sv[j][2], Sv[j][3]));
  }
#pragma unroll
  for (int h = 0; h < 2; h++) {
   mx[h] = fmaxf(mx[h], __shfl_xor_sync(~0u, mx[h], 1));
   mx[h] = fmaxf(mx[h], __shfl_xor_sync(~0u, mx[h], 2));
   if (t == 0) sMx[nb*128 + rr[h]] = mx[h];
  }
  __syncthreads();
  if (kt < SS/64 - 1) stage_kv(sb, tid, b, kt + 1, 1 - vb);

  const int par = kt & 1;
  float mn[2], sc[2], rs[2];
#pragma unroll
  for (int h = 0; h < 2; h++) {
   float mp = sM[par*128 + rr[h]];
   mn[h] = fmaxf(mp, fmaxf(sMx[rr[h]], sMx[128 + rr[h]]));
   sc[h] = __expf(mp - mn[h]);
   rs[h] = 0.f;
  }
#pragma unroll
  for (int j = 0; j < 4; j++) {
#pragma unroll
   for (int h = 0; h < 2; h++) {
    float pa = __expf(Sv[j][2*h] - mn[h]);
    float pb = __expf(Sv[j][2*h+1] - mn[h]);
    rs[h] += pa + pb;
    u32 po = (rr[h]*PST + nb*32 + j*8 + 2*t)*2;
    *(__half2*)(sm + SMP + po) = __floats2half2_rn(pa, pb);
   }
  }
#pragma unroll
  for (int h = 0; h < 2; h++) {
   rs[h] += __shfl_xor_sync(~0u, rs[h], 1);
   rs[h] += __shfl_xor_sync(~0u, rs[h], 2);
   if (t == 0) {
    sL[nb*128 + rr[h]] = sL[nb*128 + rr[h]]*sc[h] + rs[h];
    if (nb == 0) sM[(par^1)*128 + rr[h]] = mn[h];
   }
  }
#pragma unroll
  for (int j = 0; j < 16; j++) {
   O[j][0] *= sc[0]; O[j][1] *= sc[0]; O[j][2] *= sc[1]; O[j][3] *= sc[1];
  }
  __syncthreads();
#pragma unroll
  for (int ks = 0; ks < 4; ks++) {
   u32 P1[4];
   lds(P1, sb + SMP + poff + ks*32);
#pragma unroll
   for (int pr = 0; pr < 8; pr++) {
    u32 Vf[4];
    ldt(Vf, sb + (4+vb)*TSZ + voff + ks*(16*KST*2) + pr*32);
    mmah(O[2*pr], P1, Vf[0], Vf[1]);
    mmah(O[2*pr+1], P1, Vf[2], Vf[3]);
   }
  }
  CPWAIT0();
  __syncthreads();
 }

 float i0 = 1.f/(sL[rr[0]] + sL[128+rr[0]]);
 float i1 = 1.f/(sL[rr[1]] + sL[128+rr[1]]);
#pragma unroll
 for (int j = 0; j < 16; j++) {
  size_t oa = (size_t)(b*SS + q0 + rr[0])*DD + nb*128 + j*8 + 2*t;
  size_t ob = (size_t)(b*SS + q0 + rr[1])*DD + nb*128 + j*8 + 2*t;
  *(float2*)&out[oa] = make_float2(O[j][0]*i0, O[j][1]*i0);
  *(float2*)&out[ob] = make_float2(O[j][2]*i1, O[j][3]*i1);
 }
}

extern "C" void kernel_launch(void* const* d_in, const int* in_sizes, int n_in,
                              void* d_out, int out_size) {
 cudaFuncSetAttribute(attn, cudaFuncAttributeMaxDynamicSharedMemorySize, SMT);
 cudaFuncSetAttribute(pmma, cudaFuncAttributeMaxDynamicSharedMemorySize, 92160);
 splitk<<<(BB*SS*DIN)/512, 256>>>((const float*)d_in[0], 0);
 splitk<<<(BB*SS*DIN)/512, 256>>>((const float*)d_in[1], 1);
 splitk<<<(DD*DIN)/512, 256>>>((const float*)d_in[3], 2);
 splitk<<<(DD*DIN)/512, 256>>>((const float*)d_in[5], 3);
 vconv<<<(BB*SS*DD)/1024, 256>>>((const float*)d_in[2]);
 pmma<<<512, 256, 92160>>>((const float*)d_in[4], (const float*)d_in[6]);
 attn<<<BB*(SS/128), 512, SMT>>>((const float*)d_in[7], (float*)d_out);
}